// round 9
// baseline (speedup 1.0000x reference)
#include <cuda_runtime.h>
#include <cstdint>

#define VOCAB 32000
#define EMB   256
#define UNITS 1024
#define BATCH 64
#define TLEN  512
#define N3    3072

#define GRID  128
#define TPB   512
#define NCHUNK 4           // k chunks of 128 over this CTA's 512-k half
#define NGRP  16           // barrier groups
#define GSZ   8            // CTAs per group

// -------------------- device globals (no allocation allowed) ---------------
__device__ float g_xproj[(size_t)BATCH * TLEN * N3];            // [B*T, 3U]
__device__ __align__(16) uint32_t g_hx[BATCH * UNITS];          // h  (tf32 bits)
__device__ __align__(16) uint32_t g_rhx[BATCH * UNITS];         // r*h (tf32 bits)
__device__ unsigned g_grp[NGRP * 32];   // group counters, 128B apart
__device__ unsigned g_root;

// -------------------- helpers ----------------------------------------------
__device__ __forceinline__ uint32_t f2tf32(float x) {
    uint32_t r;
    asm("cvt.rna.tf32.f32 %0, %1;" : "=r"(r) : "f"(x));
    return r;
}

__device__ __forceinline__ uint32_t s2u(const void* p) {
    uint32_t a;
    asm("{ .reg .u64 t; cvta.to.shared.u64 t, %1; cvt.u32.u64 %0, t; }"
        : "=r"(a) : "l"(p));
    return a;
}

__device__ __forceinline__ void cp_async16(uint32_t saddr, const void* gaddr) {
    asm volatile("cp.async.cg.shared.global [%0], [%1], 16;"
                 :: "r"(saddr), "l"(gaddr));
}
#define CP_COMMIT() asm volatile("cp.async.commit_group;")
#define CP_WAIT0()  asm volatile("cp.async.wait_group 0;")
#define CP_WAIT1()  asm volatile("cp.async.wait_group 1;")

#define MMA_TF32(d0,d1,d2,d3,a0,a1,a2,a3,b0,b1)                               \
    asm volatile(                                                             \
        "mma.sync.aligned.m16n8k8.row.col.f32.tf32.tf32.f32 "                 \
        "{%0,%1,%2,%3},{%4,%5,%6,%7},{%8,%9},{%0,%1,%2,%3};"                  \
        : "+f"(d0), "+f"(d1), "+f"(d2), "+f"(d3)                              \
        : "r"(a0), "r"(a1), "r"(a2), "r"(a3), "r"(b0), "r"(b1))

#define CLUSTER_SYNC() do {                                                   \
    asm volatile("barrier.cluster.arrive.aligned;" ::: "memory");             \
    asm volatile("barrier.cluster.wait.aligned;"   ::: "memory");             \
} while (0)

__device__ __forceinline__ float dsmem_ld(uint32_t saddr, uint32_t rank) {
    uint32_t ra;
    asm("mapa.shared::cluster.u32 %0, %1, %2;" : "=r"(ra) : "r"(saddr), "r"(rank));
    float v;
    asm volatile("ld.shared::cluster.f32 %0, [%1];" : "=f"(v) : "r"(ra));
    return v;
}

__device__ __forceinline__ void red_rel(unsigned* p) {
    asm volatile("red.release.gpu.global.add.u32 [%0], %1;"
                 :: "l"(p), "r"(1u) : "memory");
}
__device__ __forceinline__ unsigned ld_acq(const unsigned* p) {
    unsigned v;
    asm volatile("ld.acquire.gpu.global.u32 %0, [%1];"
                 : "=r"(v) : "l"(p) : "memory");
    return v;
}

// -------------------- hierarchical grid barrier (monotonic) ----------------
// 16 groups of 8 CTAs; leaders aggregate to root.
__device__ __forceinline__ void grid_barrier(int cta, unsigned seq)
{
    __syncthreads();
    if (threadIdx.x == 0) {
        unsigned* gc = &g_grp[(cta >> 3) * 32];
        red_rel(gc);
        if ((cta & 7) == 0) {
            while (ld_acq(gc) < seq * GSZ) { }
            red_rel(&g_root);
        }
        while (ld_acq(&g_root) < seq * NGRP) { }
    }
    __syncthreads();
}

// ---------------------------------------------------------------------------
// Kernel 1: xproj = gather(emb_table, x) @ kernel + bias  — tf32 mma.sync
// (verified; resets ALL barrier counters for replay determinism — R8 bug was
//  resetting only indices < blockDim, leaving groups 8-15 and root stale)
// ---------------------------------------------------------------------------
__global__ __launch_bounds__(256) void xproj_tf32(
    const int* __restrict__ x,
    const float* __restrict__ emb_table,
    const float* __restrict__ kernelW,
    const float* __restrict__ bias)
{
    if (blockIdx.x == 0 && blockIdx.y == 0) {
        for (int i = threadIdx.x; i < NGRP * 32; i += 256) g_grp[i] = 0;
        if (threadIdx.x == 0) g_root = 0;
    }

    __shared__ uint32_t As[128 * 20];
    __shared__ uint32_t Bs[128 * 20];

    const int tid  = threadIdx.x;
    const int wid  = tid >> 5;
    const int lane = tid & 31;
    const int gID  = lane >> 2;
    const int tig  = lane & 3;
    const int wm   = wid & 1;
    const int wn   = wid >> 1;

    const int m0 = blockIdx.y * 128;
    const int n0 = blockIdx.x * 128;

    const int arow = tid & 127;
    const int akq  = tid >> 7;
    const int token = x[m0 + arow];
    const float* aptr = emb_table + (size_t)token * EMB;

    const int bk = tid >> 4;
    const int bq = tid & 15;

    float acc[4][4][4];
#pragma unroll
    for (int mi = 0; mi < 4; mi++)
#pragma unroll
        for (int ni = 0; ni < 4; ni++)
#pragma unroll
            for (int c = 0; c < 4; c++) acc[mi][ni][c] = 0.f;

    for (int k0 = 0; k0 < EMB; k0 += 16) {
        float4 a0 = *(const float4*)(aptr + k0 + akq * 8);
        float4 a1 = *(const float4*)(aptr + k0 + akq * 8 + 4);
        const float* wr = kernelW + (size_t)(k0 + bk) * N3 + n0 + bq * 8;
        float4 b0 = *(const float4*)wr;
        float4 b1 = *(const float4*)(wr + 4);

        __syncthreads();
        uint32_t* ad = &As[arow * 20 + akq * 8];
        ad[0] = f2tf32(a0.x); ad[1] = f2tf32(a0.y);
        ad[2] = f2tf32(a0.z); ad[3] = f2tf32(a0.w);
        ad[4] = f2tf32(a1.x); ad[5] = f2tf32(a1.y);
        ad[6] = f2tf32(a1.z); ad[7] = f2tf32(a1.w);
        Bs[(bq * 8 + 0) * 20 + bk] = f2tf32(b0.x);
        Bs[(bq * 8 + 1) * 20 + bk] = f2tf32(b0.y);
        Bs[(bq * 8 + 2) * 20 + bk] = f2tf32(b0.z);
        Bs[(bq * 8 + 3) * 20 + bk] = f2tf32(b0.w);
        Bs[(bq * 8 + 4) * 20 + bk] = f2tf32(b1.x);
        Bs[(bq * 8 + 5) * 20 + bk] = f2tf32(b1.y);
        Bs[(bq * 8 + 6) * 20 + bk] = f2tf32(b1.z);
        Bs[(bq * 8 + 7) * 20 + bk] = f2tf32(b1.w);
        __syncthreads();

#pragma unroll
        for (int kt = 0; kt < 2; kt++) {
            const int kb = kt * 8;
            uint32_t af[4][4], bf[4][2];
#pragma unroll
            for (int mi = 0; mi < 4; mi++) {
                const int mr = wm * 64 + mi * 16;
                af[mi][0] = As[(mr + gID    ) * 20 + kb + tig];
                af[mi][1] = As[(mr + gID + 8) * 20 + kb + tig];
                af[mi][2] = As[(mr + gID    ) * 20 + kb + tig + 4];
                af[mi][3] = As[(mr + gID + 8) * 20 + kb + tig + 4];
            }
#pragma unroll
            for (int ni = 0; ni < 4; ni++) {
                const int nb = wn * 32 + ni * 8;
                bf[ni][0] = Bs[(nb + gID) * 20 + kb + tig];
                bf[ni][1] = Bs[(nb + gID) * 20 + kb + tig + 4];
            }
#pragma unroll
            for (int mi = 0; mi < 4; mi++)
#pragma unroll
                for (int ni = 0; ni < 4; ni++)
                    MMA_TF32(acc[mi][ni][0], acc[mi][ni][1],
                             acc[mi][ni][2], acc[mi][ni][3],
                             af[mi][0], af[mi][1], af[mi][2], af[mi][3],
                             bf[ni][0], bf[ni][1]);
        }
    }

#pragma unroll
    for (int mi = 0; mi < 4; mi++) {
#pragma unroll
        for (int ni = 0; ni < 4; ni++) {
            const int row = m0 + wm * 64 + mi * 16 + gID;
            const int col = n0 + wn * 32 + ni * 8 + 2 * tig;
            const float bz0 = bias[col], bz1 = bias[col + 1];
            float2 v0 = make_float2(acc[mi][ni][0] + bz0, acc[mi][ni][1] + bz1);
            float2 v1 = make_float2(acc[mi][ni][2] + bz0, acc[mi][ni][3] + bz1);
            *(float2*)&g_xproj[(size_t)row * N3 + col]       = v0;
            *(float2*)&g_xproj[(size_t)(row + 8) * N3 + col] = v1;
        }
    }
}

// ---------------------------------------------------------------------------
// Kernel 2: persistent GRU scan — cluster-2 split-K, 128-k chunks (3 buffers,
// prefetch distance 2), hierarchical grid barrier.
// SMEM (floats):
//   ws   [48][516]    @ 0      Wz(0-15)/Wr(16-31)/Wh(32-47) cols, tf32, k-half
//   stg  [3][64][132] @ 24768  staged h/rh chunks (64 rows x 128 k, pad 4)
//   pacc (alias stg)  @ 24768  16x528 (A) / 16x272 (B)
//   redA [64][33]     @ 50112
//   redB [64][17]     @ 52224
// total 53312 floats = 213,248 B
// ---------------------------------------------------------------------------
#define SM_WS   0
#define SM_STG  24768
#define WBUF    8448       // 64 * 132 floats per buffer
#define SM_PACC 24768
#define SM_REDA 50112
#define SM_REDB 52224
#define SMEM_FLOATS 53312

__global__ void __launch_bounds__(TPB, 1) __cluster_dims__(2, 1, 1)
gru_scan(const float* __restrict__ hidden,
         const float* __restrict__ rk,
         float* __restrict__ out)
{
    extern __shared__ float sm[];
    uint32_t* smu = (uint32_t*)sm;
    float* pacc = sm + SM_PACC;
    float* redA = sm + SM_REDA;
    float* redB = sm + SM_REDB;

    const int tid   = threadIdx.x;
    const int cta   = blockIdx.x;
    const int crank = cta & 1;        // cluster rank (k-half owner)
    const int cg    = cta >> 1;       // column group 0..63
    const uint32_t peer = crank ^ 1;

    const int wid  = tid >> 5;
    const int lane = tid & 31;
    const int gID  = lane >> 2;
    const int tig  = lane & 3;
    const int mg   = wid & 3;         // m-group: rows [mg*16, mg*16+16)
    const int ksl  = wid >> 2;        // k-slice 0..3 (32 k per 128-chunk)
    const int r0   = mg * 16 + gID;

    // gate/update mapping: 32 rows x 16 cols per CTA
    const int grow = crank * 32 + (tid >> 4);
    const int gcol = cg * 16 + (tid & 15);
    const int lcol = tid & 15;

    // reduction mapping (all 64 rows for peer)
    const int rrow = tid >> 3;
    const int rc4  = (tid & 7) * 4;
    const int rc2  = (tid & 7) * 2;
    const int rmgr = rrow >> 4;
    const int rlr  = rrow & 15;

    // ---- load weight slice (16 cols x 3 gates x 512 k) ----
    for (int idx = tid; idx < 48 * 512; idx += TPB) {
        const int r = idx >> 9;
        const int k = idx & 511;
        const int col = (r >> 4) * UNITS + cg * 16 + (r & 15);
        smu[SM_WS + r * 516 + k] = f2tf32(rk[(size_t)(crank * 512 + k) * N3 + col]);
    }

    // ---- init g_hx + register h ----
    float hreg;
    {
        int gidx = cta * TPB + tid;
        g_hx[gidx] = f2tf32(hidden[gidx]);
        hreg = hidden[grow * UNITS + gcol];
    }
    unsigned bseq = 0;
    grid_barrier(cta, ++bseq);

    // staging: 4 x 16B per thread per 128-k chunk, coalesced
    int st_r[4], st_c[4];
    uint32_t st_s[4];
#pragma unroll
    for (int i = 0; i < 4; i++) {
        int flat = i * TPB + tid;               // 0..2047
        st_r[i] = flat >> 5;                    // row 0..63
        st_c[i] = flat & 31;                    // 16B slot 0..31
        st_s[i] = s2u(&smu[SM_STG + st_r[i] * 132 + st_c[i] * 4]);
    }
    const int koff = crank * 512;

    const uint32_t* wsz0 = &smu[SM_WS + (gID     ) * 516];
    const uint32_t* wsz1 = &smu[SM_WS + (gID +  8) * 516];
    const uint32_t* wsr0 = &smu[SM_WS + (gID + 16) * 516];
    const uint32_t* wsr1 = &smu[SM_WS + (gID + 24) * 516];
    const uint32_t* wsh0 = &smu[SM_WS + (gID + 32) * 516];
    const uint32_t* wsh1 = &smu[SM_WS + (gID + 40) * 516];

    float zreg = 0.f;

    for (int t = 0; t < TLEN; t++) {
        const size_t xb = ((size_t)(grow * TLEN + t)) * N3 + gcol;
        const float xz = __ldcg(&g_xproj[xb]);
        const float xr = __ldcg(&g_xproj[xb + UNITS]);
        const float xh = __ldcg(&g_xproj[xb + 2 * UNITS]);

        // =================== Phase A: zr_partial = h @ [Wz|Wr] (half-K) ======
        {
            const uint32_t* src = g_hx;

            float az0[4], az1[4], ar0[4], ar1[4];
#pragma unroll
            for (int c = 0; c < 4; c++) { az0[c]=0.f; az1[c]=0.f; ar0[c]=0.f; ar1[c]=0.f; }

            // prologue: chunks 0,1 -> buffers 0,1
#pragma unroll
            for (int p = 0; p < 2; p++) {
#pragma unroll
                for (int i = 0; i < 4; i++)
                    cp_async16(st_s[i] + p * (WBUF * 4),
                               src + st_r[i] * 1024 + koff + p * 128 + st_c[i] * 4);
                CP_COMMIT();
            }

#pragma unroll
            for (int kc = 0; kc < NCHUNK; kc++) {
                if (kc < NCHUNK - 1) { CP_WAIT1(); } else { CP_WAIT0(); }
                __syncthreads();
                if (kc + 2 < NCHUNK) {
                    const int dst = (kc + 2) % 3;
#pragma unroll
                    for (int i = 0; i < 4; i++)
                        cp_async16(st_s[i] + dst * (WBUF * 4),
                                   src + st_r[i] * 1024 + koff + (kc + 2) * 128 + st_c[i] * 4);
                    CP_COMMIT();
                }

                const uint32_t* hb = &smu[SM_STG + (kc % 3) * WBUF];
#pragma unroll
                for (int kt = 0; kt < 4; kt++) {
                    const int c0 = ksl * 32 + kt * 8 + tig;
                    uint32_t a0 = hb[(r0    ) * 132 + c0];
                    uint32_t a1 = hb[(r0 + 8) * 132 + c0];
                    uint32_t a2 = hb[(r0    ) * 132 + c0 + 4];
                    uint32_t a3 = hb[(r0 + 8) * 132 + c0 + 4];
                    const int kw = kc * 128 + ksl * 32 + kt * 8 + tig;
                    MMA_TF32(az0[0], az0[1], az0[2], az0[3], a0, a1, a2, a3, wsz0[kw], wsz0[kw + 4]);
                    MMA_TF32(az1[0], az1[1], az1[2], az1[3], a0, a1, a2, a3, wsz1[kw], wsz1[kw + 4]);
                    MMA_TF32(ar0[0], ar0[1], ar0[2], ar0[3], a0, a1, a2, a3, wsr0[kw], wsr0[kw + 4]);
                    MMA_TF32(ar1[0], ar1[1], ar1[2], ar1[3], a0, a1, a2, a3, wsr1[kw], wsr1[kw + 4]);
                }
            }

            __syncthreads();   // staging done before pacc alias

            // warp partials: C[16x32], row stride 33
            float* pw = pacc + wid * 528;
            pw[(gID    ) * 33 +  0 + 2 * tig    ] = az0[0];
            pw[(gID    ) * 33 +  0 + 2 * tig + 1] = az0[1];
            pw[(gID + 8) * 33 +  0 + 2 * tig    ] = az0[2];
            pw[(gID + 8) * 33 +  0 + 2 * tig + 1] = az0[3];
            pw[(gID    ) * 33 +  8 + 2 * tig    ] = az1[0];
            pw[(gID    ) * 33 +  8 + 2 * tig + 1] = az1[1];
            pw[(gID + 8) * 33 +  8 + 2 * tig    ] = az1[2];
            pw[(gID + 8) * 33 +  8 + 2 * tig + 1] = az1[3];
            pw[(gID    ) * 33 + 16 + 2 * tig    ] = ar0[0];
            pw[(gID    ) * 33 + 16 + 2 * tig + 1] = ar0[1];
            pw[(gID + 8) * 33 + 16 + 2 * tig    ] = ar0[2];
            pw[(gID + 8) * 33 + 16 + 2 * tig + 1] = ar0[3];
            pw[(gID    ) * 33 + 24 + 2 * tig    ] = ar1[0];
            pw[(gID    ) * 33 + 24 + 2 * tig + 1] = ar1[1];
            pw[(gID + 8) * 33 + 24 + 2 * tig    ] = ar1[2];
            pw[(gID + 8) * 33 + 24 + 2 * tig + 1] = ar1[3];
            __syncthreads();

            // reduce 4 k-slices -> redA[64][33]
            {
                float s0 = 0.f, s1 = 0.f, s2 = 0.f, s3 = 0.f;
#pragma unroll
                for (int s = 0; s < 4; s++) {
                    const float* p = pacc + (s * 4 + rmgr) * 528 + rlr * 33 + rc4;
                    s0 += p[0]; s1 += p[1]; s2 += p[2]; s3 += p[3];
                }
                float* rd = redA + rrow * 33 + rc4;
                rd[0] = s0; rd[1] = s1; rd[2] = s2; rd[3] = s3;
            }
            CLUSTER_SYNC();

            // gates: own + peer half-K partial (DSMEM)
            {
                const uint32_t zloc = s2u(&redA[grow * 33 + lcol]);
                const uint32_t rloc = s2u(&redA[grow * 33 + 16 + lcol]);
                float zp = sm[SM_REDA + grow * 33 + lcol]      + dsmem_ld(zloc, peer);
                float rp = sm[SM_REDA + grow * 33 + 16 + lcol] + dsmem_ld(rloc, peer);
                float z = 1.f / (1.f + __expf(-(xz + zp)));
                float r = 1.f / (1.f + __expf(-(xr + rp)));
                g_rhx[grow * UNITS + gcol] = f2tf32(r * hreg);
                zreg = z;
            }
        }
        grid_barrier(cta, ++bseq);

        // =================== Phase B: mh_partial = rh @ Wh (half-K) ==========
        {
            const uint32_t* src = g_rhx;

            float ah0[4], ah1[4];
#pragma unroll
            for (int c = 0; c < 4; c++) { ah0[c] = 0.f; ah1[c] = 0.f; }

#pragma unroll
            for (int p = 0; p < 2; p++) {
#pragma unroll
                for (int i = 0; i < 4; i++)
                    cp_async16(st_s[i] + p * (WBUF * 4),
                               src + st_r[i] * 1024 + koff + p * 128 + st_c[i] * 4);
                CP_COMMIT();
            }

#pragma unroll
            for (int kc = 0; kc < NCHUNK; kc++) {
                if (kc < NCHUNK - 1) { CP_WAIT1(); } else { CP_WAIT0(); }
                __syncthreads();
                if (kc + 2 < NCHUNK) {
                    const int dst = (kc + 2) % 3;
#pragma unroll
                    for (int i = 0; i < 4; i++)
                        cp_async16(st_s[i] + dst * (WBUF * 4),
                                   src + st_r[i] * 1024 + koff + (kc + 2) * 128 + st_c[i] * 4);
                    CP_COMMIT();
                }

                const uint32_t* hb = &smu[SM_STG + (kc % 3) * WBUF];
#pragma unroll
                for (int kt = 0; kt < 4; kt++) {
                    const int c0 = ksl * 32 + kt * 8 + tig;
                    uint32_t a0 = hb[(r0    ) * 132 + c0];
                    uint32_t a1 = hb[(r0 + 8) * 132 + c0];
                    uint32_t a2 = hb[(r0    ) * 132 + c0 + 4];
                    uint32_t a3 = hb[(r0 + 8) * 132 + c0 + 4];
                    const int kw = kc * 128 + ksl * 32 + kt * 8 + tig;
                    MMA_TF32(ah0[0], ah0[1], ah0[2], ah0[3], a0, a1, a2, a3, wsh0[kw], wsh0[kw + 4]);
                    MMA_TF32(ah1[0], ah1[1], ah1[2], ah1[3], a0, a1, a2, a3, wsh1[kw], wsh1[kw + 4]);
                }
            }

            __syncthreads();

            // warp partials: C[16x16], row stride 17
            float* pw = pacc + wid * 272;
            pw[(gID    ) * 17 + 0 + 2 * tig    ] = ah0[0];
            pw[(gID    ) * 17 + 0 + 2 * tig + 1] = ah0[1];
            pw[(gID + 8) * 17 + 0 + 2 * tig    ] = ah0[2];
            pw[(gID + 8) * 17 + 0 + 2 * tig + 1] = ah0[3];
            pw[(gID    ) * 17 + 8 + 2 * tig    ] = ah1[0];
            pw[(gID    ) * 17 + 8 + 2 * tig + 1] = ah1[1];
            pw[(gID + 8) * 17 + 8 + 2 * tig    ] = ah1[2];
            pw[(gID + 8) * 17 + 8 + 2 * tig + 1] = ah1[3];
            __syncthreads();

            // reduce 4 k-slices -> redB[64][17]
            {
                float s0 = 0.f, s1 = 0.f;
#pragma unroll
                for (int s = 0; s < 4; s++) {
                    const float* p = pacc + (s * 4 + rmgr) * 272 + rlr * 17 + rc2;
                    s0 += p[0]; s1 += p[1];
                }
                float* rd = redB + rrow * 17 + rc2;
                rd[0] = s0; rd[1] = s1;
            }
            CLUSTER_SYNC();

            // h update: own + peer partial
            {
                const uint32_t hlocA = s2u(&redB[grow * 17 + lcol]);
                float mp = sm[SM_REDB + grow * 17 + lcol] + dsmem_ld(hlocA, peer);
                const float a = xh + mp;
                const float hh = 1.f - 2.f / (1.f + __expf(2.f * a));  // tanh(a)
                const float hn = zreg * hreg + (1.f - zreg) * hh;
                hreg = hn;
                g_hx[grow * UNITS + gcol] = f2tf32(hn);
                out[((size_t)(grow * TLEN + t)) * UNITS + gcol] = hn;
                if (t == TLEN - 1)
                    out[(size_t)BATCH * TLEN * UNITS + (size_t)grow * UNITS + gcol] = hn;
            }
        }
        grid_barrier(cta, ++bseq);
    }
}

// ---------------------------------------------------------------------------
extern "C" void kernel_launch(void* const* d_in, const int* in_sizes, int n_in,
                              void* d_out, int out_size)
{
    const int*   x      = (const int*)d_in[0];
    const float* hidden = (const float*)d_in[1];
    const float* emb    = (const float*)d_in[2];
    const float* kern   = (const float*)d_in[3];
    const float* rk     = (const float*)d_in[4];
    const float* bias   = (const float*)d_in[5];
    float* out = (float*)d_out;

    static bool attr_set = false;
    if (!attr_set) {
        cudaFuncSetAttribute(gru_scan, cudaFuncAttributeMaxDynamicSharedMemorySize,
                             SMEM_FLOATS * sizeof(float));
        attr_set = true;
    }

    // Node 1: projection GEMM (tf32, fused embedding gather) + barrier reset
    xproj_tf32<<<dim3(N3 / 128, (BATCH * TLEN) / 128), 256>>>(x, emb, kern, bias);

    // Node 2: persistent GRU scan (cluster-2 split-K, hierarchical barrier)
    gru_scan<<<GRID, TPB, SMEM_FLOATS * sizeof(float)>>>(hidden, rk, out);
}

// round 10
// speedup vs baseline: 1.6186x; 1.6186x over previous
#include <cuda_runtime.h>
#include <cstdint>

#define VOCAB 32000
#define EMB   256
#define UNITS 1024
#define BATCH 64
#define TLEN  512
#define N3    3072

#define GRID  128
#define NCLUS 64
#define TPB   512
#define NCHUNK 8           // k chunks of 64 over this CTA's 512-k half

// -------------------- device globals (no allocation allowed) ---------------
__device__ float g_xproj[(size_t)BATCH * TLEN * N3];            // [B*T, 3U]
__device__ __align__(16) uint32_t g_hx[BATCH * UNITS];          // h  (tf32 bits)
__device__ __align__(16) uint32_t g_rhx[BATCH * UNITS];         // r*h (tf32 bits)
__device__ unsigned g_count = 0;

// -------------------- helpers ----------------------------------------------
__device__ __forceinline__ uint32_t f2tf32(float x) {
    uint32_t r;
    asm("cvt.rna.tf32.f32 %0, %1;" : "=r"(r) : "f"(x));
    return r;
}

__device__ __forceinline__ uint32_t s2u(const void* p) {
    uint32_t a;
    asm("{ .reg .u64 t; cvta.to.shared.u64 t, %1; cvt.u32.u64 %0, t; }"
        : "=r"(a) : "l"(p));
    return a;
}

__device__ __forceinline__ void cp_async16(uint32_t saddr, const void* gaddr) {
    asm volatile("cp.async.cg.shared.global [%0], [%1], 16;"
                 :: "r"(saddr), "l"(gaddr));
}
#define CP_COMMIT() asm volatile("cp.async.commit_group;")
#define CP_WAIT0()  asm volatile("cp.async.wait_group 0;")
#define CP_WAIT1()  asm volatile("cp.async.wait_group 1;")
#define CP_WAIT2()  asm volatile("cp.async.wait_group 2;")

#define MMA_TF32(d0,d1,d2,d3,a0,a1,a2,a3,b0,b1)                               \
    asm volatile(                                                             \
        "mma.sync.aligned.m16n8k8.row.col.f32.tf32.tf32.f32 "                 \
        "{%0,%1,%2,%3},{%4,%5,%6,%7},{%8,%9},{%0,%1,%2,%3};"                  \
        : "+f"(d0), "+f"(d1), "+f"(d2), "+f"(d3)                              \
        : "r"(a0), "r"(a1), "r"(a2), "r"(a3), "r"(b0), "r"(b1))

#define CLUSTER_SYNC() do {                                                   \
    asm volatile("barrier.cluster.arrive.aligned;" ::: "memory");             \
    asm volatile("barrier.cluster.wait.aligned;"   ::: "memory");             \
} while (0)

__device__ __forceinline__ float dsmem_ld(uint32_t saddr, uint32_t rank) {
    uint32_t ra;
    asm("mapa.shared::cluster.u32 %0, %1, %2;" : "=r"(ra) : "r"(saddr), "r"(rank));
    float v;
    asm volatile("ld.shared::cluster.f32 %0, [%1];" : "=f"(v) : "r"(ra));
    return v;
}

__device__ __forceinline__ void red_rel(unsigned* p) {
    asm volatile("red.release.gpu.global.add.u32 [%0], %1;"
                 :: "l"(p), "r"(1u) : "memory");
}
__device__ __forceinline__ unsigned ld_acq(const unsigned* p) {
    unsigned v;
    asm volatile("ld.acquire.gpu.global.u32 %0, [%1];"
                 : "=r"(v) : "l"(p) : "memory");
    return v;
}

// ---- grid barrier: one arrival per CLUSTER (rank0 after cluster sync), ----
// ---- monotonic counter, everyone polls. Target = seq * NCLUS.          ----
__device__ __forceinline__ void grid_barrier(int crank, unsigned seq)
{
    __syncthreads();
    CLUSTER_SYNC();     // peer's global writes visible (cluster-scope acq_rel)
    if (threadIdx.x == 0) {
        if (crank == 0) red_rel(&g_count);
        unsigned v;
        do { v = ld_acq(&g_count); } while (v < seq * NCLUS);
    }
    __syncthreads();
}

// ---------------------------------------------------------------------------
// Kernel 1: xproj = gather(emb_table, x) @ kernel + bias  — tf32 mma.sync
// (verified; resets g_count for replay determinism)
// ---------------------------------------------------------------------------
__global__ __launch_bounds__(256) void xproj_tf32(
    const int* __restrict__ x,
    const float* __restrict__ emb_table,
    const float* __restrict__ kernelW,
    const float* __restrict__ bias)
{
    if (blockIdx.x == 0 && blockIdx.y == 0 && threadIdx.x == 0)
        g_count = 0;

    __shared__ uint32_t As[128 * 20];
    __shared__ uint32_t Bs[128 * 20];

    const int tid  = threadIdx.x;
    const int wid  = tid >> 5;
    const int lane = tid & 31;
    const int gID  = lane >> 2;
    const int tig  = lane & 3;
    const int wm   = wid & 1;
    const int wn   = wid >> 1;

    const int m0 = blockIdx.y * 128;
    const int n0 = blockIdx.x * 128;

    const int arow = tid & 127;
    const int akq  = tid >> 7;
    const int token = x[m0 + arow];
    const float* aptr = emb_table + (size_t)token * EMB;

    const int bk = tid >> 4;
    const int bq = tid & 15;

    float acc[4][4][4];
#pragma unroll
    for (int mi = 0; mi < 4; mi++)
#pragma unroll
        for (int ni = 0; ni < 4; ni++)
#pragma unroll
            for (int c = 0; c < 4; c++) acc[mi][ni][c] = 0.f;

    for (int k0 = 0; k0 < EMB; k0 += 16) {
        float4 a0 = *(const float4*)(aptr + k0 + akq * 8);
        float4 a1 = *(const float4*)(aptr + k0 + akq * 8 + 4);
        const float* wr = kernelW + (size_t)(k0 + bk) * N3 + n0 + bq * 8;
        float4 b0 = *(const float4*)wr;
        float4 b1 = *(const float4*)(wr + 4);

        __syncthreads();
        uint32_t* ad = &As[arow * 20 + akq * 8];
        ad[0] = f2tf32(a0.x); ad[1] = f2tf32(a0.y);
        ad[2] = f2tf32(a0.z); ad[3] = f2tf32(a0.w);
        ad[4] = f2tf32(a1.x); ad[5] = f2tf32(a1.y);
        ad[6] = f2tf32(a1.z); ad[7] = f2tf32(a1.w);
        Bs[(bq * 8 + 0) * 20 + bk] = f2tf32(b0.x);
        Bs[(bq * 8 + 1) * 20 + bk] = f2tf32(b0.y);
        Bs[(bq * 8 + 2) * 20 + bk] = f2tf32(b0.z);
        Bs[(bq * 8 + 3) * 20 + bk] = f2tf32(b0.w);
        Bs[(bq * 8 + 4) * 20 + bk] = f2tf32(b1.x);
        Bs[(bq * 8 + 5) * 20 + bk] = f2tf32(b1.y);
        Bs[(bq * 8 + 6) * 20 + bk] = f2tf32(b1.z);
        Bs[(bq * 8 + 7) * 20 + bk] = f2tf32(b1.w);
        __syncthreads();

#pragma unroll
        for (int kt = 0; kt < 2; kt++) {
            const int kb = kt * 8;
            uint32_t af[4][4], bf[4][2];
#pragma unroll
            for (int mi = 0; mi < 4; mi++) {
                const int mr = wm * 64 + mi * 16;
                af[mi][0] = As[(mr + gID    ) * 20 + kb + tig];
                af[mi][1] = As[(mr + gID + 8) * 20 + kb + tig];
                af[mi][2] = As[(mr + gID    ) * 20 + kb + tig + 4];
                af[mi][3] = As[(mr + gID + 8) * 20 + kb + tig + 4];
            }
#pragma unroll
            for (int ni = 0; ni < 4; ni++) {
                const int nb = wn * 32 + ni * 8;
                bf[ni][0] = Bs[(nb + gID) * 20 + kb + tig];
                bf[ni][1] = Bs[(nb + gID) * 20 + kb + tig + 4];
            }
#pragma unroll
            for (int mi = 0; mi < 4; mi++)
#pragma unroll
                for (int ni = 0; ni < 4; ni++)
                    MMA_TF32(acc[mi][ni][0], acc[mi][ni][1],
                             acc[mi][ni][2], acc[mi][ni][3],
                             af[mi][0], af[mi][1], af[mi][2], af[mi][3],
                             bf[ni][0], bf[ni][1]);
        }
    }

#pragma unroll
    for (int mi = 0; mi < 4; mi++) {
#pragma unroll
        for (int ni = 0; ni < 4; ni++) {
            const int row = m0 + wm * 64 + mi * 16 + gID;
            const int col = n0 + wn * 32 + ni * 8 + 2 * tig;
            const float bz0 = bias[col], bz1 = bias[col + 1];
            float2 v0 = make_float2(acc[mi][ni][0] + bz0, acc[mi][ni][1] + bz1);
            float2 v1 = make_float2(acc[mi][ni][2] + bz0, acc[mi][ni][3] + bz1);
            *(float2*)&g_xproj[(size_t)row * N3 + col]       = v0;
            *(float2*)&g_xproj[(size_t)(row + 8) * N3 + col] = v1;
        }
    }
}

// ---------------------------------------------------------------------------
// Kernel 2: persistent GRU scan — cluster-2 split-K (exact R7 structure),
// cluster-deduplicated grid barrier (the ONE change vs R7).
// SMEM (floats):
//   ws   [48][516]   @ 0      Wz(0-15)/Wr(16-31)/Wh(32-47) cols, tf32, k-half
//   stg  [4][64][68] @ 24768  staged h/rh chunks (64 rows x 64 k, pad 4)
//   pacc (alias stg) @ 24768  16x528 (A) / 16x272 (B)
//   redA [64][33]    @ 42176
//   redB [64][17]    @ 44288
// total 45376 floats = 181,504 B
// ---------------------------------------------------------------------------
#define SM_WS   0
#define SM_STG  24768
#define WBUF    4352       // 64 * 68 floats per buffer
#define SM_PACC 24768
#define SM_REDA 42176
#define SM_REDB 44288
#define SMEM_FLOATS 45376

__global__ void __launch_bounds__(TPB, 1) __cluster_dims__(2, 1, 1)
gru_scan(const float* __restrict__ hidden,
         const float* __restrict__ rk,
         float* __restrict__ out)
{
    extern __shared__ float sm[];
    uint32_t* smu = (uint32_t*)sm;
    float* pacc = sm + SM_PACC;
    float* redA = sm + SM_REDA;
    float* redB = sm + SM_REDB;

    const int tid   = threadIdx.x;
    const int cta   = blockIdx.x;
    const int crank = cta & 1;        // cluster rank (k-half owner)
    const int cg    = cta >> 1;       // column group 0..63
    const uint32_t peer = crank ^ 1;

    const int wid  = tid >> 5;
    const int lane = tid & 31;
    const int gID  = lane >> 2;
    const int tig  = lane & 3;
    const int mg   = wid & 3;         // m-group: rows [mg*16, mg*16+16)
    const int ksl  = wid >> 2;        // k-slice 0..3 (16 k per 64-chunk)
    const int r0   = mg * 16 + gID;

    // gate/update mapping: 32 rows x 16 cols per CTA
    const int grow = crank * 32 + (tid >> 4);
    const int gcol = cg * 16 + (tid & 15);
    const int lcol = tid & 15;

    // reduction mapping (all 64 rows for peer)
    const int rrow = tid >> 3;
    const int rc4  = (tid & 7) * 4;
    const int rc2  = (tid & 7) * 2;
    const int rmgr = rrow >> 4;
    const int rlr  = rrow & 15;

    // ---- load weight slice (16 cols x 3 gates x 512 k) ----
    for (int idx = tid; idx < 48 * 512; idx += TPB) {
        const int r = idx >> 9;
        const int k = idx & 511;
        const int col = (r >> 4) * UNITS + cg * 16 + (r & 15);
        smu[SM_WS + r * 516 + k] = f2tf32(rk[(size_t)(crank * 512 + k) * N3 + col]);
    }

    // ---- init g_hx + register h ----
    float hreg;
    {
        int gidx = cta * TPB + tid;
        g_hx[gidx] = f2tf32(hidden[gidx]);
        hreg = hidden[grow * UNITS + gcol];
    }
    unsigned bseq = 0;
    grid_barrier(crank, ++bseq);

    // staging: 2 x 16B per thread per 64-k chunk, coalesced
    int st_r[2], st_c[2];
    uint32_t st_s[2];
#pragma unroll
    for (int i = 0; i < 2; i++) {
        int flat = i * TPB + tid;               // 0..1023
        st_r[i] = flat >> 4;                    // row 0..63
        st_c[i] = flat & 15;                    // 16B slot 0..15
        st_s[i] = s2u(&smu[SM_STG + st_r[i] * 68 + st_c[i] * 4]);
    }
    const int koff = crank * 512;

    const uint32_t* wsz0 = &smu[SM_WS + (gID     ) * 516];
    const uint32_t* wsz1 = &smu[SM_WS + (gID +  8) * 516];
    const uint32_t* wsr0 = &smu[SM_WS + (gID + 16) * 516];
    const uint32_t* wsr1 = &smu[SM_WS + (gID + 24) * 516];
    const uint32_t* wsh0 = &smu[SM_WS + (gID + 32) * 516];
    const uint32_t* wsh1 = &smu[SM_WS + (gID + 40) * 516];

    float zreg = 0.f;

    for (int t = 0; t < TLEN; t++) {
        const size_t xb = ((size_t)(grow * TLEN + t)) * N3 + gcol;
        const float xz = __ldcg(&g_xproj[xb]);
        const float xr = __ldcg(&g_xproj[xb + UNITS]);
        const float xh = __ldcg(&g_xproj[xb + 2 * UNITS]);

        // =================== Phase A: zr_partial = h @ [Wz|Wr] (half-K) ======
        {
            const uint32_t* src = g_hx;

            float az0[4], az1[4], ar0[4], ar1[4];
#pragma unroll
            for (int c = 0; c < 4; c++) { az0[c]=0.f; az1[c]=0.f; ar0[c]=0.f; ar1[c]=0.f; }

#pragma unroll
            for (int p = 0; p < 3; p++) {
#pragma unroll
                for (int i = 0; i < 2; i++)
                    cp_async16(st_s[i] + p * (WBUF * 4),
                               src + st_r[i] * 1024 + koff + p * 64 + st_c[i] * 4);
                CP_COMMIT();
            }

#pragma unroll
            for (int kc = 0; kc < NCHUNK; kc++) {
                if (kc < NCHUNK - 2)      { CP_WAIT2(); }
                else if (kc == NCHUNK - 2){ CP_WAIT1(); }
                else                      { CP_WAIT0(); }
                __syncthreads();
                if (kc + 3 < NCHUNK) {
#pragma unroll
                    for (int i = 0; i < 2; i++)
                        cp_async16(st_s[i] + ((kc + 3) & 3) * (WBUF * 4),
                                   src + st_r[i] * 1024 + koff + (kc + 3) * 64 + st_c[i] * 4);
                    CP_COMMIT();
                }

                const uint32_t* hb = &smu[SM_STG + (kc & 3) * WBUF];
#pragma unroll
                for (int kt = 0; kt < 2; kt++) {
                    const int c0 = ksl * 16 + kt * 8 + tig;
                    uint32_t a0 = hb[(r0    ) * 68 + c0];
                    uint32_t a1 = hb[(r0 + 8) * 68 + c0];
                    uint32_t a2 = hb[(r0    ) * 68 + c0 + 4];
                    uint32_t a3 = hb[(r0 + 8) * 68 + c0 + 4];
                    const int kw = kc * 64 + ksl * 16 + kt * 8 + tig;
                    MMA_TF32(az0[0], az0[1], az0[2], az0[3], a0, a1, a2, a3, wsz0[kw], wsz0[kw + 4]);
                    MMA_TF32(az1[0], az1[1], az1[2], az1[3], a0, a1, a2, a3, wsz1[kw], wsz1[kw + 4]);
                    MMA_TF32(ar0[0], ar0[1], ar0[2], ar0[3], a0, a1, a2, a3, wsr0[kw], wsr0[kw + 4]);
                    MMA_TF32(ar1[0], ar1[1], ar1[2], ar1[3], a0, a1, a2, a3, wsr1[kw], wsr1[kw + 4]);
                }
            }

            __syncthreads();   // staging done before pacc alias

            // warp partials: C[16x32], row stride 33
            float* pw = pacc + wid * 528;
            pw[(gID    ) * 33 +  0 + 2 * tig    ] = az0[0];
            pw[(gID    ) * 33 +  0 + 2 * tig + 1] = az0[1];
            pw[(gID + 8) * 33 +  0 + 2 * tig    ] = az0[2];
            pw[(gID + 8) * 33 +  0 + 2 * tig + 1] = az0[3];
            pw[(gID    ) * 33 +  8 + 2 * tig    ] = az1[0];
            pw[(gID    ) * 33 +  8 + 2 * tig + 1] = az1[1];
            pw[(gID + 8) * 33 +  8 + 2 * tig    ] = az1[2];
            pw[(gID + 8) * 33 +  8 + 2 * tig + 1] = az1[3];
            pw[(gID    ) * 33 + 16 + 2 * tig    ] = ar0[0];
            pw[(gID    ) * 33 + 16 + 2 * tig + 1] = ar0[1];
            pw[(gID + 8) * 33 + 16 + 2 * tig    ] = ar0[2];
            pw[(gID + 8) * 33 + 16 + 2 * tig + 1] = ar0[3];
            pw[(gID    ) * 33 + 24 + 2 * tig    ] = ar1[0];
            pw[(gID    ) * 33 + 24 + 2 * tig + 1] = ar1[1];
            pw[(gID + 8) * 33 + 24 + 2 * tig    ] = ar1[2];
            pw[(gID + 8) * 33 + 24 + 2 * tig + 1] = ar1[3];
            __syncthreads();

            // reduce 4 k-slices -> redA[64][33]
            {
                float s0 = 0.f, s1 = 0.f, s2 = 0.f, s3 = 0.f;
#pragma unroll
                for (int s = 0; s < 4; s++) {
                    const float* p = pacc + (s * 4 + rmgr) * 528 + rlr * 33 + rc4;
                    s0 += p[0]; s1 += p[1]; s2 += p[2]; s3 += p[3];
                }
                float* rd = redA + rrow * 33 + rc4;
                rd[0] = s0; rd[1] = s1; rd[2] = s2; rd[3] = s3;
            }
            CLUSTER_SYNC();

            // gates: own + peer half-K partial (DSMEM)
            {
                const uint32_t zloc = s2u(&redA[grow * 33 + lcol]);
                const uint32_t rloc = s2u(&redA[grow * 33 + 16 + lcol]);
                float zp = sm[SM_REDA + grow * 33 + lcol]      + dsmem_ld(zloc, peer);
                float rp = sm[SM_REDA + grow * 33 + 16 + lcol] + dsmem_ld(rloc, peer);
                float z = 1.f / (1.f + __expf(-(xz + zp)));
                float r = 1.f / (1.f + __expf(-(xr + rp)));
                g_rhx[grow * UNITS + gcol] = f2tf32(r * hreg);
                zreg = z;
            }
        }
        grid_barrier(crank, ++bseq);

        // =================== Phase B: mh_partial = rh @ Wh (half-K) ==========
        {
            const uint32_t* src = g_rhx;

            float ah0[4], ah1[4];
#pragma unroll
            for (int c = 0; c < 4; c++) { ah0[c] = 0.f; ah1[c] = 0.f; }

#pragma unroll
            for (int p = 0; p < 3; p++) {
#pragma unroll
                for (int i = 0; i < 2; i++)
                    cp_async16(st_s[i] + p * (WBUF * 4),
                               src + st_r[i] * 1024 + koff + p * 64 + st_c[i] * 4);
                CP_COMMIT();
            }

#pragma unroll
            for (int kc = 0; kc < NCHUNK; kc++) {
                if (kc < NCHUNK - 2)      { CP_WAIT2(); }
                else if (kc == NCHUNK - 2){ CP_WAIT1(); }
                else                      { CP_WAIT0(); }
                __syncthreads();
                if (kc + 3 < NCHUNK) {
#pragma unroll
                    for (int i = 0; i < 2; i++)
                        cp_async16(st_s[i] + ((kc + 3) & 3) * (WBUF * 4),
                                   src + st_r[i] * 1024 + koff + (kc + 3) * 64 + st_c[i] * 4);
                    CP_COMMIT();
                }

                const uint32_t* hb = &smu[SM_STG + (kc & 3) * WBUF];
#pragma unroll
                for (int kt = 0; kt < 2; kt++) {
                    const int c0 = ksl * 16 + kt * 8 + tig;
                    uint32_t a0 = hb[(r0    ) * 68 + c0];
                    uint32_t a1 = hb[(r0 + 8) * 68 + c0];
                    uint32_t a2 = hb[(r0    ) * 68 + c0 + 4];
                    uint32_t a3 = hb[(r0 + 8) * 68 + c0 + 4];
                    const int kw = kc * 64 + ksl * 16 + kt * 8 + tig;
                    MMA_TF32(ah0[0], ah0[1], ah0[2], ah0[3], a0, a1, a2, a3, wsh0[kw], wsh0[kw + 4]);
                    MMA_TF32(ah1[0], ah1[1], ah1[2], ah1[3], a0, a1, a2, a3, wsh1[kw], wsh1[kw + 4]);
                }
            }

            __syncthreads();

            // warp partials: C[16x16], row stride 17
            float* pw = pacc + wid * 272;
            pw[(gID    ) * 17 + 0 + 2 * tig    ] = ah0[0];
            pw[(gID    ) * 17 + 0 + 2 * tig + 1] = ah0[1];
            pw[(gID + 8) * 17 + 0 + 2 * tig    ] = ah0[2];
            pw[(gID + 8) * 17 + 0 + 2 * tig + 1] = ah0[3];
            pw[(gID    ) * 17 + 8 + 2 * tig    ] = ah1[0];
            pw[(gID    ) * 17 + 8 + 2 * tig + 1] = ah1[1];
            pw[(gID + 8) * 17 + 8 + 2 * tig    ] = ah1[2];
            pw[(gID + 8) * 17 + 8 + 2 * tig + 1] = ah1[3];
            __syncthreads();

            // reduce 4 k-slices -> redB[64][17]
            {
                float s0 = 0.f, s1 = 0.f;
#pragma unroll
                for (int s = 0; s < 4; s++) {
                    const float* p = pacc + (s * 4 + rmgr) * 272 + rlr * 17 + rc2;
                    s0 += p[0]; s1 += p[1];
                }
                float* rd = redB + rrow * 17 + rc2;
                rd[0] = s0; rd[1] = s1;
            }
            CLUSTER_SYNC();

            // h update: own + peer partial
            {
                const uint32_t hlocA = s2u(&redB[grow * 17 + lcol]);
                float mp = sm[SM_REDB + grow * 17 + lcol] + dsmem_ld(hlocA, peer);
                const float a = xh + mp;
                const float hh = 1.f - 2.f / (1.f + __expf(2.f * a));  // tanh(a)
                const float hn = zreg * hreg + (1.f - zreg) * hh;
                hreg = hn;
                g_hx[grow * UNITS + gcol] = f2tf32(hn);
                out[((size_t)(grow * TLEN + t)) * UNITS + gcol] = hn;
                if (t == TLEN - 1)
                    out[(size_t)BATCH * TLEN * UNITS + (size_t)grow * UNITS + gcol] = hn;
            }
        }
        grid_barrier(crank, ++bseq);
    }
}

// ---------------------------------------------------------------------------
extern "C" void kernel_launch(void* const* d_in, const int* in_sizes, int n_in,
                              void* d_out, int out_size)
{
    const int*   x      = (const int*)d_in[0];
    const float* hidden = (const float*)d_in[1];
    const float* emb    = (const float*)d_in[2];
    const float* kern   = (const float*)d_in[3];
    const float* rk     = (const float*)d_in[4];
    const float* bias   = (const float*)d_in[5];
    float* out = (float*)d_out;

    static bool attr_set = false;
    if (!attr_set) {
        cudaFuncSetAttribute(gru_scan, cudaFuncAttributeMaxDynamicSharedMemorySize,
                             SMEM_FLOATS * sizeof(float));
        attr_set = true;
    }

    // Node 1: projection GEMM (tf32, fused embedding gather) + barrier reset
    xproj_tf32<<<dim3(N3 / 128, (BATCH * TLEN) / 128), 256>>>(x, emb, kern, bias);

    // Node 2: persistent GRU scan (cluster-2 split-K, dedup barrier)
    gru_scan<<<GRID, TPB, SMEM_FLOATS * sizeof(float)>>>(hidden, rk, out);
}

// round 11
// speedup vs baseline: 1.7855x; 1.1032x over previous
#include <cuda_runtime.h>
#include <cstdint>

#define VOCAB 32000
#define EMB   256
#define UNITS 1024
#define BATCH 64
#define TLEN  512
#define N3    3072

#define GRID  128
#define TPB   512
#define NCHUNK 8           // k chunks of 64 over this CTA's 512-k half

// -------------------- device globals (no allocation allowed) ---------------
__device__ float g_xproj[(size_t)BATCH * TLEN * N3];            // [B*T, 3U]
__device__ __align__(16) uint32_t g_hx[BATCH * UNITS];          // h  (tf32 bits)
__device__ __align__(16) uint32_t g_rhx[BATCH * UNITS];         // r*h (tf32 bits)
__device__ unsigned g_count = 0;

// -------------------- helpers ----------------------------------------------
__device__ __forceinline__ uint32_t f2tf32(float x) {
    uint32_t r;
    asm("cvt.rna.tf32.f32 %0, %1;" : "=r"(r) : "f"(x));
    return r;
}

__device__ __forceinline__ uint32_t s2u(const void* p) {
    uint32_t a;
    asm("{ .reg .u64 t; cvta.to.shared.u64 t, %1; cvt.u32.u64 %0, t; }"
        : "=r"(a) : "l"(p));
    return a;
}

__device__ __forceinline__ void cp_async16(uint32_t saddr, const void* gaddr) {
    asm volatile("cp.async.cg.shared.global [%0], [%1], 16;"
                 :: "r"(saddr), "l"(gaddr));
}
#define CP_COMMIT() asm volatile("cp.async.commit_group;")
#define CP_WAIT0()  asm volatile("cp.async.wait_group 0;")
#define CP_WAIT1()  asm volatile("cp.async.wait_group 1;")
#define CP_WAIT2()  asm volatile("cp.async.wait_group 2;")

#define MMA_TF32(d0,d1,d2,d3,a0,a1,a2,a3,b0,b1)                               \
    asm volatile(                                                             \
        "mma.sync.aligned.m16n8k8.row.col.f32.tf32.tf32.f32 "                 \
        "{%0,%1,%2,%3},{%4,%5,%6,%7},{%8,%9},{%0,%1,%2,%3};"                  \
        : "+f"(d0), "+f"(d1), "+f"(d2), "+f"(d3)                              \
        : "r"(a0), "r"(a1), "r"(a2), "r"(a3), "r"(b0), "r"(b1))

#define CLUSTER_SYNC() do {                                                   \
    asm volatile("barrier.cluster.arrive.aligned;" ::: "memory");             \
    asm volatile("barrier.cluster.wait.aligned;"   ::: "memory");             \
} while (0)

__device__ __forceinline__ float dsmem_ld(uint32_t saddr, uint32_t rank) {
    uint32_t ra;
    asm("mapa.shared::cluster.u32 %0, %1, %2;" : "=r"(ra) : "r"(saddr), "r"(rank));
    float v;
    asm volatile("ld.shared::cluster.f32 %0, [%1];" : "=f"(v) : "r"(ra));
    return v;
}

// -------------------- grid barrier: monotonic release/acquire (R7) ---------
__device__ __forceinline__ void grid_barrier(unsigned target)
{
    __syncthreads();
    if (threadIdx.x == 0) {
        unsigned* cnt = &g_count;
        asm volatile("red.release.gpu.global.add.u32 [%0], %1;"
                     :: "l"(cnt), "r"(1u) : "memory");
        unsigned v;
        do {
            asm volatile("ld.acquire.gpu.global.u32 %0, [%1];"
                         : "=r"(v) : "l"(cnt) : "memory");
        } while (v < target);
    }
    __syncthreads();
}

// ---------------------------------------------------------------------------
// Kernel 1: xproj = gather(emb_table, x) @ kernel + bias  — tf32 mma.sync
// R11: cp.async double-buffered k-pipeline (16 chunks of k=16).
// SMEM: As[2][128][20] raw fp32 (gathered A rows), Bs[2][16][136] raw fp32.
// cvt to tf32 happens at fragment-load time (same rna rounding as before).
// Resets g_count for replay determinism.
// ---------------------------------------------------------------------------
#define XKC   16           // k per chunk
#define XNCH  (EMB / XKC)  // 16 chunks
#define ASTR  20           // A row stride (floats)
#define BSTR  136          // B row stride (floats)

__global__ __launch_bounds__(256) void xproj_tf32(
    const int* __restrict__ x,
    const float* __restrict__ emb_table,
    const float* __restrict__ kernelW,
    const float* __restrict__ bias)
{
    if (blockIdx.x == 0 && blockIdx.y == 0 && threadIdx.x == 0)
        g_count = 0;

    __shared__ __align__(16) float As[2][128 * ASTR];
    __shared__ __align__(16) float Bs[2][XKC * BSTR];

    const int tid  = threadIdx.x;
    const int wid  = tid >> 5;
    const int lane = tid & 31;
    const int gID  = lane >> 2;
    const int tig  = lane & 3;
    const int wm   = wid & 1;          // rows wm*64
    const int wn   = wid >> 1;         // cols wn*32

    const int m0 = blockIdx.y * 128;
    const int n0 = blockIdx.x * 128;

    // A gather mapping: thread -> (row, 2 x 16B slots)
    const int arow = tid & 127;
    const int ahalf = tid >> 7;                    // 0/1 -> float offset half*8
    const int token = x[m0 + arow];
    const float* aptr = emb_table + (size_t)token * EMB;
    const uint32_t a_s0 = s2u(&As[0][arow * ASTR + ahalf * 8]);
    const int abuf_delta = (int)(s2u(&As[1][0]) - s2u(&As[0][0]));

    // B load mapping: thread -> (krow, 2 x 16B slots)
    const int bkrow = tid >> 4;                    // 0..15
    const int bseg  = tid & 15;                    // 8 floats each
    const uint32_t b_s0 = s2u(&Bs[0][bkrow * BSTR + bseg * 8]);
    const int bbuf_delta = (int)(s2u(&Bs[1][0]) - s2u(&Bs[0][0]));

    float acc[4][4][4];
#pragma unroll
    for (int mi = 0; mi < 4; mi++)
#pragma unroll
        for (int ni = 0; ni < 4; ni++)
#pragma unroll
            for (int c = 0; c < 4; c++) acc[mi][ni][c] = 0.f;

    // prologue: stage chunk 0 into buffer 0
    {
        const float* ag = aptr + ahalf * 8;
        cp_async16(a_s0,      ag);
        cp_async16(a_s0 + 16, ag + 4);
        const float* bg = kernelW + (size_t)bkrow * N3 + n0 + bseg * 8;
        cp_async16(b_s0,      bg);
        cp_async16(b_s0 + 16, bg + 4);
        CP_COMMIT();
    }

    for (int kc = 0; kc < XNCH; kc++) {
        const int buf = kc & 1;
        if (kc + 1 < XNCH) {
            const int nb = (kc + 1) & 1;
            const float* ag = aptr + (kc + 1) * XKC + ahalf * 8;
            cp_async16(a_s0 + nb * abuf_delta,      ag);
            cp_async16(a_s0 + nb * abuf_delta + 16, ag + 4);
            const float* bg = kernelW + (size_t)((kc + 1) * XKC + bkrow) * N3 + n0 + bseg * 8;
            cp_async16(b_s0 + nb * bbuf_delta,      bg);
            cp_async16(b_s0 + nb * bbuf_delta + 16, bg + 4);
            CP_COMMIT();
            CP_WAIT1();
        } else {
            CP_WAIT0();
        }
        __syncthreads();

        const float* Ab = As[buf];
        const float* Bb = Bs[buf];
#pragma unroll
        for (int kt = 0; kt < 2; kt++) {
            const int kb = kt * 8;
            uint32_t af[4][4], bf[4][2];
#pragma unroll
            for (int mi = 0; mi < 4; mi++) {
                const int mr = wm * 64 + mi * 16;
                af[mi][0] = f2tf32(Ab[(mr + gID    ) * ASTR + kb + tig]);
                af[mi][1] = f2tf32(Ab[(mr + gID + 8) * ASTR + kb + tig]);
                af[mi][2] = f2tf32(Ab[(mr + gID    ) * ASTR + kb + tig + 4]);
                af[mi][3] = f2tf32(Ab[(mr + gID + 8) * ASTR + kb + tig + 4]);
            }
#pragma unroll
            for (int ni = 0; ni < 4; ni++) {
                const int nb2 = wn * 32 + ni * 8 + gID;
                bf[ni][0] = f2tf32(Bb[(kb + tig    ) * BSTR + nb2]);
                bf[ni][1] = f2tf32(Bb[(kb + tig + 4) * BSTR + nb2]);
            }
#pragma unroll
            for (int mi = 0; mi < 4; mi++)
#pragma unroll
                for (int ni = 0; ni < 4; ni++)
                    MMA_TF32(acc[mi][ni][0], acc[mi][ni][1],
                             acc[mi][ni][2], acc[mi][ni][3],
                             af[mi][0], af[mi][1], af[mi][2], af[mi][3],
                             bf[ni][0], bf[ni][1]);
        }
        __syncthreads();   // buffer free before next-next prefetch overwrites it
    }

    // epilogue: bias + store (unchanged from verified version)
#pragma unroll
    for (int mi = 0; mi < 4; mi++) {
#pragma unroll
        for (int ni = 0; ni < 4; ni++) {
            const int row = m0 + wm * 64 + mi * 16 + gID;
            const int col = n0 + wn * 32 + ni * 8 + 2 * tig;
            const float bz0 = bias[col], bz1 = bias[col + 1];
            float2 v0 = make_float2(acc[mi][ni][0] + bz0, acc[mi][ni][1] + bz1);
            float2 v1 = make_float2(acc[mi][ni][2] + bz0, acc[mi][ni][3] + bz1);
            *(float2*)&g_xproj[(size_t)row * N3 + col]       = v0;
            *(float2*)&g_xproj[(size_t)(row + 8) * N3 + col] = v1;
        }
    }
}

// ---------------------------------------------------------------------------
// Kernel 2: persistent GRU scan — cluster-2 split-K. EXACT R7 (6635us) code.
// SMEM (floats):
//   ws   [48][516]   @ 0      Wz(0-15)/Wr(16-31)/Wh(32-47) cols, tf32, k-half
//   stg  [4][64][68] @ 24768  staged h/rh chunks (64 rows x 64 k, pad 4)
//   pacc (alias stg) @ 24768  16x528 (A) / 16x272 (B)
//   redA [64][33]    @ 42176
//   redB [64][17]    @ 44288
// total 45376 floats = 181,504 B
// ---------------------------------------------------------------------------
#define SM_WS   0
#define SM_STG  24768
#define WBUF    4352       // 64 * 68 floats per buffer
#define SM_PACC 24768
#define SM_REDA 42176
#define SM_REDB 44288
#define SMEM_FLOATS 45376

__global__ void __launch_bounds__(TPB, 1) __cluster_dims__(2, 1, 1)
gru_scan(const float* __restrict__ hidden,
         const float* __restrict__ rk,
         float* __restrict__ out)
{
    extern __shared__ float sm[];
    uint32_t* smu = (uint32_t*)sm;
    float* pacc = sm + SM_PACC;
    float* redA = sm + SM_REDA;
    float* redB = sm + SM_REDB;

    const int tid   = threadIdx.x;
    const int cta   = blockIdx.x;
    const int crank = cta & 1;        // cluster rank (k-half owner)
    const int cg    = cta >> 1;       // column group 0..63
    const uint32_t peer = crank ^ 1;

    const int wid  = tid >> 5;
    const int lane = tid & 31;
    const int gID  = lane >> 2;
    const int tig  = lane & 3;
    const int mg   = wid & 3;         // m-group: rows [mg*16, mg*16+16)
    const int ksl  = wid >> 2;        // k-slice 0..3 (16 k per 64-chunk)
    const int r0   = mg * 16 + gID;

    // gate/update mapping: 32 rows x 16 cols per CTA
    const int grow = crank * 32 + (tid >> 4);
    const int gcol = cg * 16 + (tid & 15);
    const int lcol = tid & 15;

    // reduction mapping (all 64 rows for peer)
    const int rrow = tid >> 3;
    const int rc4  = (tid & 7) * 4;
    const int rc2  = (tid & 7) * 2;
    const int rmgr = rrow >> 4;
    const int rlr  = rrow & 15;

    // ---- load weight slice (16 cols x 3 gates x 512 k) ----
    for (int idx = tid; idx < 48 * 512; idx += TPB) {
        const int r = idx >> 9;
        const int k = idx & 511;
        const int col = (r >> 4) * UNITS + cg * 16 + (r & 15);
        smu[SM_WS + r * 516 + k] = f2tf32(rk[(size_t)(crank * 512 + k) * N3 + col]);
    }

    // ---- init g_hx + register h ----
    float hreg;
    {
        int gidx = cta * TPB + tid;
        g_hx[gidx] = f2tf32(hidden[gidx]);
        hreg = hidden[grow * UNITS + gcol];
    }
    unsigned bseq = 0;
    grid_barrier(++bseq * GRID);

    // staging: 2 x 16B per thread per 64-k chunk, coalesced
    int st_r[2], st_c[2];
    uint32_t st_s[2];
#pragma unroll
    for (int i = 0; i < 2; i++) {
        int flat = i * TPB + tid;               // 0..1023
        st_r[i] = flat >> 4;                    // row 0..63
        st_c[i] = flat & 15;                    // 16B slot 0..15
        st_s[i] = s2u(&smu[SM_STG + st_r[i] * 68 + st_c[i] * 4]);
    }
    const int koff = crank * 512;

    const uint32_t* wsz0 = &smu[SM_WS + (gID     ) * 516];
    const uint32_t* wsz1 = &smu[SM_WS + (gID +  8) * 516];
    const uint32_t* wsr0 = &smu[SM_WS + (gID + 16) * 516];
    const uint32_t* wsr1 = &smu[SM_WS + (gID + 24) * 516];
    const uint32_t* wsh0 = &smu[SM_WS + (gID + 32) * 516];
    const uint32_t* wsh1 = &smu[SM_WS + (gID + 40) * 516];

    float zreg = 0.f;

    for (int t = 0; t < TLEN; t++) {
        const size_t xb = ((size_t)(grow * TLEN + t)) * N3 + gcol;
        const float xz = __ldcg(&g_xproj[xb]);
        const float xr = __ldcg(&g_xproj[xb + UNITS]);
        const float xh = __ldcg(&g_xproj[xb + 2 * UNITS]);

        // =================== Phase A: zr_partial = h @ [Wz|Wr] (half-K) ======
        {
            const uint32_t* src = g_hx;

            float az0[4], az1[4], ar0[4], ar1[4];
#pragma unroll
            for (int c = 0; c < 4; c++) { az0[c]=0.f; az1[c]=0.f; ar0[c]=0.f; ar1[c]=0.f; }

#pragma unroll
            for (int p = 0; p < 3; p++) {
#pragma unroll
                for (int i = 0; i < 2; i++)
                    cp_async16(st_s[i] + p * (WBUF * 4),
                               src + st_r[i] * 1024 + koff + p * 64 + st_c[i] * 4);
                CP_COMMIT();
            }

#pragma unroll
            for (int kc = 0; kc < NCHUNK; kc++) {
                if (kc < NCHUNK - 2)      { CP_WAIT2(); }
                else if (kc == NCHUNK - 2){ CP_WAIT1(); }
                else                      { CP_WAIT0(); }
                __syncthreads();
                if (kc + 3 < NCHUNK) {
#pragma unroll
                    for (int i = 0; i < 2; i++)
                        cp_async16(st_s[i] + ((kc + 3) & 3) * (WBUF * 4),
                                   src + st_r[i] * 1024 + koff + (kc + 3) * 64 + st_c[i] * 4);
                    CP_COMMIT();
                }

                const uint32_t* hb = &smu[SM_STG + (kc & 3) * WBUF];
#pragma unroll
                for (int kt = 0; kt < 2; kt++) {
                    const int c0 = ksl * 16 + kt * 8 + tig;
                    uint32_t a0 = hb[(r0    ) * 68 + c0];
                    uint32_t a1 = hb[(r0 + 8) * 68 + c0];
                    uint32_t a2 = hb[(r0    ) * 68 + c0 + 4];
                    uint32_t a3 = hb[(r0 + 8) * 68 + c0 + 4];
                    const int kw = kc * 64 + ksl * 16 + kt * 8 + tig;
                    MMA_TF32(az0[0], az0[1], az0[2], az0[3], a0, a1, a2, a3, wsz0[kw], wsz0[kw + 4]);
                    MMA_TF32(az1[0], az1[1], az1[2], az1[3], a0, a1, a2, a3, wsz1[kw], wsz1[kw + 4]);
                    MMA_TF32(ar0[0], ar0[1], ar0[2], ar0[3], a0, a1, a2, a3, wsr0[kw], wsr0[kw + 4]);
                    MMA_TF32(ar1[0], ar1[1], ar1[2], ar1[3], a0, a1, a2, a3, wsr1[kw], wsr1[kw + 4]);
                }
            }

            __syncthreads();   // staging done before pacc alias

            // warp partials: C[16x32], row stride 33
            float* pw = pacc + wid * 528;
            pw[(gID    ) * 33 +  0 + 2 * tig    ] = az0[0];
            pw[(gID    ) * 33 +  0 + 2 * tig + 1] = az0[1];
            pw[(gID + 8) * 33 +  0 + 2 * tig    ] = az0[2];
            pw[(gID + 8) * 33 +  0 + 2 * tig + 1] = az0[3];
            pw[(gID    ) * 33 +  8 + 2 * tig    ] = az1[0];
            pw[(gID    ) * 33 +  8 + 2 * tig + 1] = az1[1];
            pw[(gID + 8) * 33 +  8 + 2 * tig    ] = az1[2];
            pw[(gID + 8) * 33 +  8 + 2 * tig + 1] = az1[3];
            pw[(gID    ) * 33 + 16 + 2 * tig    ] = ar0[0];
            pw[(gID    ) * 33 + 16 + 2 * tig + 1] = ar0[1];
            pw[(gID + 8) * 33 + 16 + 2 * tig    ] = ar0[2];
            pw[(gID + 8) * 33 + 16 + 2 * tig + 1] = ar0[3];
            pw[(gID    ) * 33 + 24 + 2 * tig    ] = ar1[0];
            pw[(gID    ) * 33 + 24 + 2 * tig + 1] = ar1[1];
            pw[(gID + 8) * 33 + 24 + 2 * tig    ] = ar1[2];
            pw[(gID + 8) * 33 + 24 + 2 * tig + 1] = ar1[3];
            __syncthreads();

            // reduce 4 k-slices -> redA[64][33]
            {
                float s0 = 0.f, s1 = 0.f, s2 = 0.f, s3 = 0.f;
#pragma unroll
                for (int s = 0; s < 4; s++) {
                    const float* p = pacc + (s * 4 + rmgr) * 528 + rlr * 33 + rc4;
                    s0 += p[0]; s1 += p[1]; s2 += p[2]; s3 += p[3];
                }
                float* rd = redA + rrow * 33 + rc4;
                rd[0] = s0; rd[1] = s1; rd[2] = s2; rd[3] = s3;
            }
            CLUSTER_SYNC();

            // gates: own + peer half-K partial (DSMEM)
            {
                const uint32_t zloc = s2u(&redA[grow * 33 + lcol]);
                const uint32_t rloc = s2u(&redA[grow * 33 + 16 + lcol]);
                float zp = sm[SM_REDA + grow * 33 + lcol]      + dsmem_ld(zloc, peer);
                float rp = sm[SM_REDA + grow * 33 + 16 + lcol] + dsmem_ld(rloc, peer);
                float z = 1.f / (1.f + __expf(-(xz + zp)));
                float r = 1.f / (1.f + __expf(-(xr + rp)));
                g_rhx[grow * UNITS + gcol] = f2tf32(r * hreg);
                zreg = z;
            }
        }
        grid_barrier(++bseq * GRID);

        // =================== Phase B: mh_partial = rh @ Wh (half-K) ==========
        {
            const uint32_t* src = g_rhx;

            float ah0[4], ah1[4];
#pragma unroll
            for (int c = 0; c < 4; c++) { ah0[c] = 0.f; ah1[c] = 0.f; }

#pragma unroll
            for (int p = 0; p < 3; p++) {
#pragma unroll
                for (int i = 0; i < 2; i++)
                    cp_async16(st_s[i] + p * (WBUF * 4),
                               src + st_r[i] * 1024 + koff + p * 64 + st_c[i] * 4);
                CP_COMMIT();
            }

#pragma unroll
            for (int kc = 0; kc < NCHUNK; kc++) {
                if (kc < NCHUNK - 2)      { CP_WAIT2(); }
                else if (kc == NCHUNK - 2){ CP_WAIT1(); }
                else                      { CP_WAIT0(); }
                __syncthreads();
                if (kc + 3 < NCHUNK) {
#pragma unroll
                    for (int i = 0; i < 2; i++)
                        cp_async16(st_s[i] + ((kc + 3) & 3) * (WBUF * 4),
                                   src + st_r[i] * 1024 + koff + (kc + 3) * 64 + st_c[i] * 4);
                    CP_COMMIT();
                }

                const uint32_t* hb = &smu[SM_STG + (kc & 3) * WBUF];
#pragma unroll
                for (int kt = 0; kt < 2; kt++) {
                    const int c0 = ksl * 16 + kt * 8 + tig;
                    uint32_t a0 = hb[(r0    ) * 68 + c0];
                    uint32_t a1 = hb[(r0 + 8) * 68 + c0];
                    uint32_t a2 = hb[(r0    ) * 68 + c0 + 4];
                    uint32_t a3 = hb[(r0 + 8) * 68 + c0 + 4];
                    const int kw = kc * 64 + ksl * 16 + kt * 8 + tig;
                    MMA_TF32(ah0[0], ah0[1], ah0[2], ah0[3], a0, a1, a2, a3, wsh0[kw], wsh0[kw + 4]);
                    MMA_TF32(ah1[0], ah1[1], ah1[2], ah1[3], a0, a1, a2, a3, wsh1[kw], wsh1[kw + 4]);
                }
            }

            __syncthreads();

            // warp partials: C[16x16], row stride 17
            float* pw = pacc + wid * 272;
            pw[(gID    ) * 17 + 0 + 2 * tig    ] = ah0[0];
            pw[(gID    ) * 17 + 0 + 2 * tig + 1] = ah0[1];
            pw[(gID + 8) * 17 + 0 + 2 * tig    ] = ah0[2];
            pw[(gID + 8) * 17 + 0 + 2 * tig + 1] = ah0[3];
            pw[(gID    ) * 17 + 8 + 2 * tig    ] = ah1[0];
            pw[(gID    ) * 17 + 8 + 2 * tig + 1] = ah1[1];
            pw[(gID + 8) * 17 + 8 + 2 * tig    ] = ah1[2];
            pw[(gID + 8) * 17 + 8 + 2 * tig + 1] = ah1[3];
            __syncthreads();

            // reduce 4 k-slices -> redB[64][17]
            {
                float s0 = 0.f, s1 = 0.f;
#pragma unroll
                for (int s = 0; s < 4; s++) {
                    const float* p = pacc + (s * 4 + rmgr) * 272 + rlr * 17 + rc2;
                    s0 += p[0]; s1 += p[1];
                }
                float* rd = redB + rrow * 17 + rc2;
                rd[0] = s0; rd[1] = s1;
            }
            CLUSTER_SYNC();

            // h update: own + peer partial
            {
                const uint32_t hlocA = s2u(&redB[grow * 17 + lcol]);
                float mp = sm[SM_REDB + grow * 17 + lcol] + dsmem_ld(hlocA, peer);
                const float a = xh + mp;
                const float hh = 1.f - 2.f / (1.f + __expf(2.f * a));  // tanh(a)
                const float hn = zreg * hreg + (1.f - zreg) * hh;
                hreg = hn;
                g_hx[grow * UNITS + gcol] = f2tf32(hn);
                out[((size_t)(grow * TLEN + t)) * UNITS + gcol] = hn;
                if (t == TLEN - 1)
                    out[(size_t)BATCH * TLEN * UNITS + (size_t)grow * UNITS + gcol] = hn;
            }
        }
        grid_barrier(++bseq * GRID);
    }
}

// ---------------------------------------------------------------------------
extern "C" void kernel_launch(void* const* d_in, const int* in_sizes, int n_in,
                              void* d_out, int out_size)
{
    const int*   x      = (const int*)d_in[0];
    const float* hidden = (const float*)d_in[1];
    const float* emb    = (const float*)d_in[2];
    const float* kern   = (const float*)d_in[3];
    const float* rk     = (const float*)d_in[4];
    const float* bias   = (const float*)d_in[5];
    float* out = (float*)d_out;

    static bool attr_set = false;
    if (!attr_set) {
        cudaFuncSetAttribute(gru_scan, cudaFuncAttributeMaxDynamicSharedMemorySize,
                             SMEM_FLOATS * sizeof(float));
        attr_set = true;
    }

    // Node 1: projection GEMM (tf32, cp.async pipelined) + barrier reset
    xproj_tf32<<<dim3(N3 / 128, (BATCH * TLEN) / 128), 256>>>(x, emb, kern, bias);

    // Node 2: persistent GRU scan (cluster-2 split-K, R7-verbatim)
    gru_scan<<<GRID, TPB, SMEM_FLOATS * sizeof(float)>>>(hidden, rk, out);
}

// round 12
// speedup vs baseline: 2.0766x; 1.1630x over previous
#include <cuda_runtime.h>
#include <cuda_fp16.h>
#include <cstdint>

#define VOCAB 32000
#define EMB   256
#define UNITS 1024
#define BATCH 64
#define TLEN  512
#define N3    3072

#define GRID  128
#define TPB   512
#define NCHUNK 8           // k chunks of 64 over this CTA's 512-k half

// -------------------- device globals (no allocation allowed) ---------------
__device__ float g_xproj[(size_t)BATCH * TLEN * N3];            // [B*T, 3U]
__device__ __align__(16) __half g_hx[BATCH * UNITS];            // h  (fp16)
__device__ __align__(16) __half g_rhx[BATCH * UNITS];           // r*h (fp16)
__device__ unsigned g_count = 0;

// -------------------- helpers ----------------------------------------------
__device__ __forceinline__ uint32_t f2tf32(float x) {
    uint32_t r;
    asm("cvt.rna.tf32.f32 %0, %1;" : "=r"(r) : "f"(x));
    return r;
}

__device__ __forceinline__ uint32_t pack_h2(float lo, float hi) {
    __half2 h = __floats2half2_rn(lo, hi);
    return *(uint32_t*)&h;
}

__device__ __forceinline__ uint32_t s2u(const void* p) {
    uint32_t a;
    asm("{ .reg .u64 t; cvta.to.shared.u64 t, %1; cvt.u32.u64 %0, t; }"
        : "=r"(a) : "l"(p));
    return a;
}

__device__ __forceinline__ void cp_async16(uint32_t saddr, const void* gaddr) {
    asm volatile("cp.async.cg.shared.global [%0], [%1], 16;"
                 :: "r"(saddr), "l"(gaddr));
}
#define CP_COMMIT() asm volatile("cp.async.commit_group;")
#define CP_WAIT0()  asm volatile("cp.async.wait_group 0;")
#define CP_WAIT1()  asm volatile("cp.async.wait_group 1;")
#define CP_WAIT2()  asm volatile("cp.async.wait_group 2;")

#define MMA_TF32(d0,d1,d2,d3,a0,a1,a2,a3,b0,b1)                               \
    asm volatile(                                                             \
        "mma.sync.aligned.m16n8k8.row.col.f32.tf32.tf32.f32 "                 \
        "{%0,%1,%2,%3},{%4,%5,%6,%7},{%8,%9},{%0,%1,%2,%3};"                  \
        : "+f"(d0), "+f"(d1), "+f"(d2), "+f"(d3)                              \
        : "r"(a0), "r"(a1), "r"(a2), "r"(a3), "r"(b0), "r"(b1))

#define MMA_F16(d0,d1,d2,d3,a0,a1,a2,a3,b0,b1)                                \
    asm volatile(                                                             \
        "mma.sync.aligned.m16n8k16.row.col.f32.f16.f16.f32 "                  \
        "{%0,%1,%2,%3},{%4,%5,%6,%7},{%8,%9},{%0,%1,%2,%3};"                  \
        : "+f"(d0), "+f"(d1), "+f"(d2), "+f"(d3)                              \
        : "r"(a0), "r"(a1), "r"(a2), "r"(a3), "r"(b0), "r"(b1))

#define CLUSTER_SYNC() do {                                                   \
    asm volatile("barrier.cluster.arrive.aligned;" ::: "memory");             \
    asm volatile("barrier.cluster.wait.aligned;"   ::: "memory");             \
} while (0)

__device__ __forceinline__ float dsmem_ld(uint32_t saddr, uint32_t rank) {
    uint32_t ra;
    asm("mapa.shared::cluster.u32 %0, %1, %2;" : "=r"(ra) : "r"(saddr), "r"(rank));
    float v;
    asm volatile("ld.shared::cluster.f32 %0, [%1];" : "=f"(v) : "r"(ra));
    return v;
}

// -------------------- grid barrier: monotonic release/acquire --------------
__device__ __forceinline__ void grid_barrier(unsigned target)
{
    __syncthreads();
    if (threadIdx.x == 0) {
        unsigned* cnt = &g_count;
        asm volatile("red.release.gpu.global.add.u32 [%0], %1;"
                     :: "l"(cnt), "r"(1u) : "memory");
        unsigned v;
        do {
            asm volatile("ld.acquire.gpu.global.u32 %0, [%1];"
                         : "=r"(v) : "l"(cnt) : "memory");
        } while (v < target);
    }
    __syncthreads();
}

// ---------------------------------------------------------------------------
// Kernel 1: xproj = gather(emb_table, x) @ kernel + bias — tf32 mma.sync,
// cp.async double-buffered (R11-verbatim, verified). Resets g_count.
// ---------------------------------------------------------------------------
#define XKC   16
#define XNCH  (EMB / XKC)
#define ASTR  20
#define BSTR  136

__global__ __launch_bounds__(256) void xproj_tf32(
    const int* __restrict__ x,
    const float* __restrict__ emb_table,
    const float* __restrict__ kernelW,
    const float* __restrict__ bias)
{
    if (blockIdx.x == 0 && blockIdx.y == 0 && threadIdx.x == 0)
        g_count = 0;

    __shared__ __align__(16) float As[2][128 * ASTR];
    __shared__ __align__(16) float Bs[2][XKC * BSTR];

    const int tid  = threadIdx.x;
    const int wid  = tid >> 5;
    const int lane = tid & 31;
    const int gID  = lane >> 2;
    const int tig  = lane & 3;
    const int wm   = wid & 1;
    const int wn   = wid >> 1;

    const int m0 = blockIdx.y * 128;
    const int n0 = blockIdx.x * 128;

    const int arow = tid & 127;
    const int ahalf = tid >> 7;
    const int token = x[m0 + arow];
    const float* aptr = emb_table + (size_t)token * EMB;
    const uint32_t a_s0 = s2u(&As[0][arow * ASTR + ahalf * 8]);
    const int abuf_delta = (int)(s2u(&As[1][0]) - s2u(&As[0][0]));

    const int bkrow = tid >> 4;
    const int bseg  = tid & 15;
    const uint32_t b_s0 = s2u(&Bs[0][bkrow * BSTR + bseg * 8]);
    const int bbuf_delta = (int)(s2u(&Bs[1][0]) - s2u(&Bs[0][0]));

    float acc[4][4][4];
#pragma unroll
    for (int mi = 0; mi < 4; mi++)
#pragma unroll
        for (int ni = 0; ni < 4; ni++)
#pragma unroll
            for (int c = 0; c < 4; c++) acc[mi][ni][c] = 0.f;

    {
        const float* ag = aptr + ahalf * 8;
        cp_async16(a_s0,      ag);
        cp_async16(a_s0 + 16, ag + 4);
        const float* bg = kernelW + (size_t)bkrow * N3 + n0 + bseg * 8;
        cp_async16(b_s0,      bg);
        cp_async16(b_s0 + 16, bg + 4);
        CP_COMMIT();
    }

    for (int kc = 0; kc < XNCH; kc++) {
        const int buf = kc & 1;
        if (kc + 1 < XNCH) {
            const int nb = (kc + 1) & 1;
            const float* ag = aptr + (kc + 1) * XKC + ahalf * 8;
            cp_async16(a_s0 + nb * abuf_delta,      ag);
            cp_async16(a_s0 + nb * abuf_delta + 16, ag + 4);
            const float* bg = kernelW + (size_t)((kc + 1) * XKC + bkrow) * N3 + n0 + bseg * 8;
            cp_async16(b_s0 + nb * bbuf_delta,      bg);
            cp_async16(b_s0 + nb * bbuf_delta + 16, bg + 4);
            CP_COMMIT();
            CP_WAIT1();
        } else {
            CP_WAIT0();
        }
        __syncthreads();

        const float* Ab = As[buf];
        const float* Bb = Bs[buf];
#pragma unroll
        for (int kt = 0; kt < 2; kt++) {
            const int kb = kt * 8;
            uint32_t af[4][4], bf[4][2];
#pragma unroll
            for (int mi = 0; mi < 4; mi++) {
                const int mr = wm * 64 + mi * 16;
                af[mi][0] = f2tf32(Ab[(mr + gID    ) * ASTR + kb + tig]);
                af[mi][1] = f2tf32(Ab[(mr + gID + 8) * ASTR + kb + tig]);
                af[mi][2] = f2tf32(Ab[(mr + gID    ) * ASTR + kb + tig + 4]);
                af[mi][3] = f2tf32(Ab[(mr + gID + 8) * ASTR + kb + tig + 4]);
            }
#pragma unroll
            for (int ni = 0; ni < 4; ni++) {
                const int nb2 = wn * 32 + ni * 8 + gID;
                bf[ni][0] = f2tf32(Bb[(kb + tig    ) * BSTR + nb2]);
                bf[ni][1] = f2tf32(Bb[(kb + tig + 4) * BSTR + nb2]);
            }
#pragma unroll
            for (int mi = 0; mi < 4; mi++)
#pragma unroll
                for (int ni = 0; ni < 4; ni++)
                    MMA_TF32(acc[mi][ni][0], acc[mi][ni][1],
                             acc[mi][ni][2], acc[mi][ni][3],
                             af[mi][0], af[mi][1], af[mi][2], af[mi][3],
                             bf[ni][0], bf[ni][1]);
        }
        __syncthreads();
    }

#pragma unroll
    for (int mi = 0; mi < 4; mi++) {
#pragma unroll
        for (int ni = 0; ni < 4; ni++) {
            const int row = m0 + wm * 64 + mi * 16 + gID;
            const int col = n0 + wn * 32 + ni * 8 + 2 * tig;
            const float bz0 = bias[col], bz1 = bias[col + 1];
            float2 v0 = make_float2(acc[mi][ni][0] + bz0, acc[mi][ni][1] + bz1);
            float2 v1 = make_float2(acc[mi][ni][2] + bz0, acc[mi][ni][3] + bz1);
            *(float2*)&g_xproj[(size_t)row * N3 + col]       = v0;
            *(float2*)&g_xproj[(size_t)(row + 8) * N3 + col] = v1;
        }
    }
}

// ---------------------------------------------------------------------------
// Kernel 2: persistent GRU scan — cluster-2 split-K, fp16 MMA (m16n8k16).
// Structure = R7-verbatim (4 buffers, prefetch distance 3, flat barrier,
// DSMEM half-K reduction); only the datapath is fp16.
// SMEM (uint32/float units):
//   ws   [48][260]  @ 0      Wz(0-15)/Wr(16-31)/Wh(32-47) cols, fp16 pairs
//   stg  [4][64][36] @ 12480 staged h/rh chunks (64 rows x 32 h2, pad 4)
//   pacc (alias stg) @ 12480 16x528 (A) / 16x272 (B), fp32
//   redA [64][33]    @ 21696
//   redB [64][17]    @ 23808
// total 24896 units = 99,584 B
// ---------------------------------------------------------------------------
#define SM_WS   0
#define SM_STG  12480
#define WBUF    2304       // 64 * 36 uint32 per buffer
#define SM_PACC 12480
#define SM_REDA 21696
#define SM_REDB 23808
#define SMEM_FLOATS 24896

__global__ void __launch_bounds__(TPB, 1) __cluster_dims__(2, 1, 1)
gru_scan(const float* __restrict__ hidden,
         const float* __restrict__ rk,
         float* __restrict__ out)
{
    extern __shared__ float sm[];
    uint32_t* smu = (uint32_t*)sm;
    float* pacc = sm + SM_PACC;
    float* redA = sm + SM_REDA;
    float* redB = sm + SM_REDB;

    const int tid   = threadIdx.x;
    const int cta   = blockIdx.x;
    const int crank = cta & 1;        // cluster rank (k-half owner)
    const int cg    = cta >> 1;       // column group 0..63
    const uint32_t peer = crank ^ 1;

    const int wid  = tid >> 5;
    const int lane = tid & 31;
    const int gID  = lane >> 2;
    const int tig  = lane & 3;
    const int mg   = wid & 3;         // m-group: rows [mg*16, mg*16+16)
    const int ksl  = wid >> 2;        // k-slice 0..3 (16 k per 64-chunk)
    const int r0   = mg * 16 + gID;

    // gate/update mapping: 32 rows x 16 cols per CTA
    const int grow = crank * 32 + (tid >> 4);
    const int gcol = cg * 16 + (tid & 15);
    const int lcol = tid & 15;

    // reduction mapping (all 64 rows for peer)
    const int rrow = tid >> 3;
    const int rc4  = (tid & 7) * 4;
    const int rc2  = (tid & 7) * 2;
    const int rmgr = rrow >> 4;
    const int rlr  = rrow & 15;

    const int koff = crank * 512;     // k base (half units)

    // ---- load weight slice as fp16 pairs (16 cols x 3 gates x 256 pairs) ----
    for (int idx = tid; idx < 48 * 256; idx += TPB) {
        const int r  = idx >> 8;                 // ws col-row 0..47
        const int kp = idx & 255;                // k-pair 0..255
        const int col = (r >> 4) * UNITS + cg * 16 + (r & 15);
        const float w0 = rk[(size_t)(koff + 2 * kp    ) * N3 + col];
        const float w1 = rk[(size_t)(koff + 2 * kp + 1) * N3 + col];
        smu[SM_WS + r * 260 + kp] = pack_h2(w0, w1);
    }

    // ---- init g_hx (fp16 of hidden) + register h ----
    float hreg;
    {
        int gidx = cta * TPB + tid;              // 128*512 = 65536 exactly
        g_hx[gidx] = __float2half_rn(hidden[gidx]);
        hreg = hidden[grow * UNITS + gcol];
    }
    unsigned bseq = 0;
    grid_barrier(++bseq * GRID);

    // staging: 1 x 16B per thread per chunk (chunk = 64 halfs = 128B per row)
    const int srow  = tid >> 3;                  // 0..63
    const int sslot = tid & 7;                   // 16B slot 0..7
    const uint32_t st_s = s2u(&smu[SM_STG + srow * 36 + sslot * 4]);
    const size_t gs_off = (size_t)(srow * UNITS + koff) * 2 + sslot * 16; // bytes

    const uint32_t* wsz0 = &smu[SM_WS + (gID     ) * 260];
    const uint32_t* wsz1 = &smu[SM_WS + (gID +  8) * 260];
    const uint32_t* wsr0 = &smu[SM_WS + (gID + 16) * 260];
    const uint32_t* wsr1 = &smu[SM_WS + (gID + 24) * 260];
    const uint32_t* wsh0 = &smu[SM_WS + (gID + 32) * 260];
    const uint32_t* wsh1 = &smu[SM_WS + (gID + 40) * 260];
    const int fcol = ksl * 8 + tig;              // frag pair-col within chunk

    float zreg = 0.f;

    for (int t = 0; t < TLEN; t++) {
        const size_t xb = ((size_t)(grow * TLEN + t)) * N3 + gcol;
        const float xz = __ldcg(&g_xproj[xb]);
        const float xr = __ldcg(&g_xproj[xb + UNITS]);
        const float xh = __ldcg(&g_xproj[xb + 2 * UNITS]);

        // =================== Phase A: zr_partial = h @ [Wz|Wr] (half-K) ======
        {
            const char* src = (const char*)g_hx + gs_off;

            float az0[4], az1[4], ar0[4], ar1[4];
#pragma unroll
            for (int c = 0; c < 4; c++) { az0[c]=0.f; az1[c]=0.f; ar0[c]=0.f; ar1[c]=0.f; }

#pragma unroll
            for (int p = 0; p < 3; p++) {
                cp_async16(st_s + p * (WBUF * 4), src + p * 128);
                CP_COMMIT();
            }

#pragma unroll
            for (int kc = 0; kc < NCHUNK; kc++) {
                if (kc < NCHUNK - 2)      { CP_WAIT2(); }
                else if (kc == NCHUNK - 2){ CP_WAIT1(); }
                else                      { CP_WAIT0(); }
                __syncthreads();
                if (kc + 3 < NCHUNK) {
                    cp_async16(st_s + ((kc + 3) & 3) * (WBUF * 4), src + (kc + 3) * 128);
                    CP_COMMIT();
                }

                const uint32_t* hb = &smu[SM_STG + (kc & 3) * WBUF];
                uint32_t a0 = hb[(r0    ) * 36 + fcol];
                uint32_t a1 = hb[(r0 + 8) * 36 + fcol];
                uint32_t a2 = hb[(r0    ) * 36 + fcol + 4];
                uint32_t a3 = hb[(r0 + 8) * 36 + fcol + 4];
                const int kw = kc * 32 + fcol;
                MMA_F16(az0[0], az0[1], az0[2], az0[3], a0, a1, a2, a3, wsz0[kw], wsz0[kw + 4]);
                MMA_F16(az1[0], az1[1], az1[2], az1[3], a0, a1, a2, a3, wsz1[kw], wsz1[kw + 4]);
                MMA_F16(ar0[0], ar0[1], ar0[2], ar0[3], a0, a1, a2, a3, wsr0[kw], wsr0[kw + 4]);
                MMA_F16(ar1[0], ar1[1], ar1[2], ar1[3], a0, a1, a2, a3, wsr1[kw], wsr1[kw + 4]);
            }

            __syncthreads();   // staging done before pacc alias

            // warp partials: C[16x32], row stride 33
            float* pw = pacc + wid * 528;
            pw[(gID    ) * 33 +  0 + 2 * tig    ] = az0[0];
            pw[(gID    ) * 33 +  0 + 2 * tig + 1] = az0[1];
            pw[(gID + 8) * 33 +  0 + 2 * tig    ] = az0[2];
            pw[(gID + 8) * 33 +  0 + 2 * tig + 1] = az0[3];
            pw[(gID    ) * 33 +  8 + 2 * tig    ] = az1[0];
            pw[(gID    ) * 33 +  8 + 2 * tig + 1] = az1[1];
            pw[(gID + 8) * 33 +  8 + 2 * tig    ] = az1[2];
            pw[(gID + 8) * 33 +  8 + 2 * tig + 1] = az1[3];
            pw[(gID    ) * 33 + 16 + 2 * tig    ] = ar0[0];
            pw[(gID    ) * 33 + 16 + 2 * tig + 1] = ar0[1];
            pw[(gID + 8) * 33 + 16 + 2 * tig    ] = ar0[2];
            pw[(gID + 8) * 33 + 16 + 2 * tig + 1] = ar0[3];
            pw[(gID    ) * 33 + 24 + 2 * tig    ] = ar1[0];
            pw[(gID    ) * 33 + 24 + 2 * tig + 1] = ar1[1];
            pw[(gID + 8) * 33 + 24 + 2 * tig    ] = ar1[2];
            pw[(gID + 8) * 33 + 24 + 2 * tig + 1] = ar1[3];
            __syncthreads();

            // reduce 4 k-slices -> redA[64][33]
            {
                float s0 = 0.f, s1 = 0.f, s2 = 0.f, s3 = 0.f;
#pragma unroll
                for (int s = 0; s < 4; s++) {
                    const float* p = pacc + (s * 4 + rmgr) * 528 + rlr * 33 + rc4;
                    s0 += p[0]; s1 += p[1]; s2 += p[2]; s3 += p[3];
                }
                float* rd = redA + rrow * 33 + rc4;
                rd[0] = s0; rd[1] = s1; rd[2] = s2; rd[3] = s3;
            }
            CLUSTER_SYNC();

            // gates: own + peer half-K partial (DSMEM)
            {
                const uint32_t zloc = s2u(&redA[grow * 33 + lcol]);
                const uint32_t rloc = s2u(&redA[grow * 33 + 16 + lcol]);
                float zp = sm[SM_REDA + grow * 33 + lcol]      + dsmem_ld(zloc, peer);
                float rp = sm[SM_REDA + grow * 33 + 16 + lcol] + dsmem_ld(rloc, peer);
                float z = 1.f / (1.f + __expf(-(xz + zp)));
                float r = 1.f / (1.f + __expf(-(xr + rp)));
                g_rhx[grow * UNITS + gcol] = __float2half_rn(r * hreg);
                zreg = z;
            }
        }
        grid_barrier(++bseq * GRID);

        // =================== Phase B: mh_partial = rh @ Wh (half-K) ==========
        {
            const char* src = (const char*)g_rhx + gs_off;

            float ah0[4], ah1[4];
#pragma unroll
            for (int c = 0; c < 4; c++) { ah0[c] = 0.f; ah1[c] = 0.f; }

#pragma unroll
            for (int p = 0; p < 3; p++) {
                cp_async16(st_s + p * (WBUF * 4), src + p * 128);
                CP_COMMIT();
            }

#pragma unroll
            for (int kc = 0; kc < NCHUNK; kc++) {
                if (kc < NCHUNK - 2)      { CP_WAIT2(); }
                else if (kc == NCHUNK - 2){ CP_WAIT1(); }
                else                      { CP_WAIT0(); }
                __syncthreads();
                if (kc + 3 < NCHUNK) {
                    cp_async16(st_s + ((kc + 3) & 3) * (WBUF * 4), src + (kc + 3) * 128);
                    CP_COMMIT();
                }

                const uint32_t* hb = &smu[SM_STG + (kc & 3) * WBUF];
                uint32_t a0 = hb[(r0    ) * 36 + fcol];
                uint32_t a1 = hb[(r0 + 8) * 36 + fcol];
                uint32_t a2 = hb[(r0    ) * 36 + fcol + 4];
                uint32_t a3 = hb[(r0 + 8) * 36 + fcol + 4];
                const int kw = kc * 32 + fcol;
                MMA_F16(ah0[0], ah0[1], ah0[2], ah0[3], a0, a1, a2, a3, wsh0[kw], wsh0[kw + 4]);
                MMA_F16(ah1[0], ah1[1], ah1[2], ah1[3], a0, a1, a2, a3, wsh1[kw], wsh1[kw + 4]);
            }

            __syncthreads();

            // warp partials: C[16x16], row stride 17
            float* pw = pacc + wid * 272;
            pw[(gID    ) * 17 + 0 + 2 * tig    ] = ah0[0];
            pw[(gID    ) * 17 + 0 + 2 * tig + 1] = ah0[1];
            pw[(gID + 8) * 17 + 0 + 2 * tig    ] = ah0[2];
            pw[(gID + 8) * 17 + 0 + 2 * tig + 1] = ah0[3];
            pw[(gID    ) * 17 + 8 + 2 * tig    ] = ah1[0];
            pw[(gID    ) * 17 + 8 + 2 * tig + 1] = ah1[1];
            pw[(gID + 8) * 17 + 8 + 2 * tig    ] = ah1[2];
            pw[(gID + 8) * 17 + 8 + 2 * tig + 1] = ah1[3];
            __syncthreads();

            // reduce 4 k-slices -> redB[64][17]
            {
                float s0 = 0.f, s1 = 0.f;
#pragma unroll
                for (int s = 0; s < 4; s++) {
                    const float* p = pacc + (s * 4 + rmgr) * 272 + rlr * 17 + rc2;
                    s0 += p[0]; s1 += p[1];
                }
                float* rd = redB + rrow * 17 + rc2;
                rd[0] = s0; rd[1] = s1;
            }
            CLUSTER_SYNC();

            // h update: own + peer partial
            {
                const uint32_t hlocA = s2u(&redB[grow * 17 + lcol]);
                float mp = sm[SM_REDB + grow * 17 + lcol] + dsmem_ld(hlocA, peer);
                const float a = xh + mp;
                const float hh = 1.f - 2.f / (1.f + __expf(2.f * a));  // tanh(a)
                const float hn = zreg * hreg + (1.f - zreg) * hh;
                hreg = hn;
                g_hx[grow * UNITS + gcol] = __float2half_rn(hn);
                out[((size_t)(grow * TLEN + t)) * UNITS + gcol] = hn;
                if (t == TLEN - 1)
                    out[(size_t)BATCH * TLEN * UNITS + (size_t)grow * UNITS + gcol] = hn;
            }
        }
        grid_barrier(++bseq * GRID);
    }
}

// ---------------------------------------------------------------------------
extern "C" void kernel_launch(void* const* d_in, const int* in_sizes, int n_in,
                              void* d_out, int out_size)
{
    const int*   x      = (const int*)d_in[0];
    const float* hidden = (const float*)d_in[1];
    const float* emb    = (const float*)d_in[2];
    const float* kern   = (const float*)d_in[3];
    const float* rk     = (const float*)d_in[4];
    const float* bias   = (const float*)d_in[5];
    float* out = (float*)d_out;

    static bool attr_set = false;
    if (!attr_set) {
        cudaFuncSetAttribute(gru_scan, cudaFuncAttributeMaxDynamicSharedMemorySize,
                             SMEM_FLOATS * sizeof(float));
        attr_set = true;
    }

    // Node 1: projection GEMM (tf32, cp.async pipelined) + barrier reset
    xproj_tf32<<<dim3(N3 / 128, (BATCH * TLEN) / 128), 256>>>(x, emb, kern, bias);

    // Node 2: persistent GRU scan (cluster-2 split-K, fp16 MMA)
    gru_scan<<<GRID, TPB, SMEM_FLOATS * sizeof(float)>>>(hidden, rk, out);
}

// round 13
// speedup vs baseline: 2.1338x; 1.0276x over previous
#include <cuda_runtime.h>
#include <cuda_fp16.h>
#include <cstdint>

#define VOCAB 32000
#define EMB   256
#define UNITS 1024
#define BATCH 64
#define TLEN  512
#define N3    3072

#define GRID  128
#define TPB   512
#define NCHUNK 8           // MMA k-iterations over this CTA's 512-k half

// -------------------- device globals (no allocation allowed) ---------------
__device__ float g_xproj[(size_t)BATCH * TLEN * N3];            // [B*T, 3U]
__device__ __align__(16) __half g_hx[BATCH * UNITS];            // h  (fp16)
__device__ __align__(16) __half g_rhx[BATCH * UNITS];           // r*h (fp16)
__device__ unsigned g_count = 0;

// -------------------- helpers ----------------------------------------------
__device__ __forceinline__ uint32_t f2tf32(float x) {
    uint32_t r;
    asm("cvt.rna.tf32.f32 %0, %1;" : "=r"(r) : "f"(x));
    return r;
}

__device__ __forceinline__ uint32_t pack_h2(float lo, float hi) {
    __half2 h = __floats2half2_rn(lo, hi);
    return *(uint32_t*)&h;
}

__device__ __forceinline__ uint32_t s2u(const void* p) {
    uint32_t a;
    asm("{ .reg .u64 t; cvta.to.shared.u64 t, %1; cvt.u32.u64 %0, t; }"
        : "=r"(a) : "l"(p));
    return a;
}

__device__ __forceinline__ void cp_async16(uint32_t saddr, const void* gaddr) {
    asm volatile("cp.async.cg.shared.global [%0], [%1], 16;"
                 :: "r"(saddr), "l"(gaddr));
}
#define CP_COMMIT() asm volatile("cp.async.commit_group;")
#define CP_WAIT0()  asm volatile("cp.async.wait_group 0;")
#define CP_WAIT1()  asm volatile("cp.async.wait_group 1;")

#define MMA_TF32(d0,d1,d2,d3,a0,a1,a2,a3,b0,b1)                               \
    asm volatile(                                                             \
        "mma.sync.aligned.m16n8k8.row.col.f32.tf32.tf32.f32 "                 \
        "{%0,%1,%2,%3},{%4,%5,%6,%7},{%8,%9},{%0,%1,%2,%3};"                  \
        : "+f"(d0), "+f"(d1), "+f"(d2), "+f"(d3)                              \
        : "r"(a0), "r"(a1), "r"(a2), "r"(a3), "r"(b0), "r"(b1))

#define MMA_F16(d0,d1,d2,d3,a0,a1,a2,a3,b0,b1)                                \
    asm volatile(                                                             \
        "mma.sync.aligned.m16n8k16.row.col.f32.f16.f16.f32 "                  \
        "{%0,%1,%2,%3},{%4,%5,%6,%7},{%8,%9},{%0,%1,%2,%3};"                  \
        : "+f"(d0), "+f"(d1), "+f"(d2), "+f"(d3)                              \
        : "r"(a0), "r"(a1), "r"(a2), "r"(a3), "r"(b0), "r"(b1))

#define CLUSTER_SYNC() do {                                                   \
    asm volatile("barrier.cluster.arrive.aligned;" ::: "memory");             \
    asm volatile("barrier.cluster.wait.aligned;"   ::: "memory");             \
} while (0)

__device__ __forceinline__ float dsmem_ld(uint32_t saddr, uint32_t rank) {
    uint32_t ra;
    asm("mapa.shared::cluster.u32 %0, %1, %2;" : "=r"(ra) : "r"(saddr), "r"(rank));
    float v;
    asm volatile("ld.shared::cluster.f32 %0, [%1];" : "=f"(v) : "r"(ra));
    return v;
}

// -------------------- grid barrier: monotonic release/acquire --------------
__device__ __forceinline__ void grid_barrier(unsigned target)
{
    __syncthreads();
    if (threadIdx.x == 0) {
        unsigned* cnt = &g_count;
        asm volatile("red.release.gpu.global.add.u32 [%0], %1;"
                     :: "l"(cnt), "r"(1u) : "memory");
        unsigned v;
        do {
            asm volatile("ld.acquire.gpu.global.u32 %0, [%1];"
                         : "=r"(v) : "l"(cnt) : "memory");
        } while (v < target);
    }
    __syncthreads();
}

// ---------------------------------------------------------------------------
// Kernel 1: xproj = gather(emb_table, x) @ kernel + bias — tf32 mma.sync,
// cp.async double-buffered (R11-verbatim, verified). Resets g_count.
// ---------------------------------------------------------------------------
#define XKC   16
#define XNCH  (EMB / XKC)
#define ASTR  20
#define BSTR  136

__global__ __launch_bounds__(256) void xproj_tf32(
    const int* __restrict__ x,
    const float* __restrict__ emb_table,
    const float* __restrict__ kernelW,
    const float* __restrict__ bias)
{
    if (blockIdx.x == 0 && blockIdx.y == 0 && threadIdx.x == 0)
        g_count = 0;

    __shared__ __align__(16) float As[2][128 * ASTR];
    __shared__ __align__(16) float Bs[2][XKC * BSTR];

    const int tid  = threadIdx.x;
    const int wid  = tid >> 5;
    const int lane = tid & 31;
    const int gID  = lane >> 2;
    const int tig  = lane & 3;
    const int wm   = wid & 1;
    const int wn   = wid >> 1;

    const int m0 = blockIdx.y * 128;
    const int n0 = blockIdx.x * 128;

    const int arow = tid & 127;
    const int ahalf = tid >> 7;
    const int token = x[m0 + arow];
    const float* aptr = emb_table + (size_t)token * EMB;
    const uint32_t a_s0 = s2u(&As[0][arow * ASTR + ahalf * 8]);
    const int abuf_delta = (int)(s2u(&As[1][0]) - s2u(&As[0][0]));

    const int bkrow = tid >> 4;
    const int bseg  = tid & 15;
    const uint32_t b_s0 = s2u(&Bs[0][bkrow * BSTR + bseg * 8]);
    const int bbuf_delta = (int)(s2u(&Bs[1][0]) - s2u(&Bs[0][0]));

    float acc[4][4][4];
#pragma unroll
    for (int mi = 0; mi < 4; mi++)
#pragma unroll
        for (int ni = 0; ni < 4; ni++)
#pragma unroll
            for (int c = 0; c < 4; c++) acc[mi][ni][c] = 0.f;

    {
        const float* ag = aptr + ahalf * 8;
        cp_async16(a_s0,      ag);
        cp_async16(a_s0 + 16, ag + 4);
        const float* bg = kernelW + (size_t)bkrow * N3 + n0 + bseg * 8;
        cp_async16(b_s0,      bg);
        cp_async16(b_s0 + 16, bg + 4);
        CP_COMMIT();
    }

    for (int kc = 0; kc < XNCH; kc++) {
        const int buf = kc & 1;
        if (kc + 1 < XNCH) {
            const int nb = (kc + 1) & 1;
            const float* ag = aptr + (kc + 1) * XKC + ahalf * 8;
            cp_async16(a_s0 + nb * abuf_delta,      ag);
            cp_async16(a_s0 + nb * abuf_delta + 16, ag + 4);
            const float* bg = kernelW + (size_t)((kc + 1) * XKC + bkrow) * N3 + n0 + bseg * 8;
            cp_async16(b_s0 + nb * bbuf_delta,      bg);
            cp_async16(b_s0 + nb * bbuf_delta + 16, bg + 4);
            CP_COMMIT();
            CP_WAIT1();
        } else {
            CP_WAIT0();
        }
        __syncthreads();

        const float* Ab = As[buf];
        const float* Bb = Bs[buf];
#pragma unroll
        for (int kt = 0; kt < 2; kt++) {
            const int kb = kt * 8;
            uint32_t af[4][4], bf[4][2];
#pragma unroll
            for (int mi = 0; mi < 4; mi++) {
                const int mr = wm * 64 + mi * 16;
                af[mi][0] = f2tf32(Ab[(mr + gID    ) * ASTR + kb + tig]);
                af[mi][1] = f2tf32(Ab[(mr + gID + 8) * ASTR + kb + tig]);
                af[mi][2] = f2tf32(Ab[(mr + gID    ) * ASTR + kb + tig + 4]);
                af[mi][3] = f2tf32(Ab[(mr + gID + 8) * ASTR + kb + tig + 4]);
            }
#pragma unroll
            for (int ni = 0; ni < 4; ni++) {
                const int nb2 = wn * 32 + ni * 8 + gID;
                bf[ni][0] = f2tf32(Bb[(kb + tig    ) * BSTR + nb2]);
                bf[ni][1] = f2tf32(Bb[(kb + tig + 4) * BSTR + nb2]);
            }
#pragma unroll
            for (int mi = 0; mi < 4; mi++)
#pragma unroll
                for (int ni = 0; ni < 4; ni++)
                    MMA_TF32(acc[mi][ni][0], acc[mi][ni][1],
                             acc[mi][ni][2], acc[mi][ni][3],
                             af[mi][0], af[mi][1], af[mi][2], af[mi][3],
                             bf[ni][0], bf[ni][1]);
        }
        __syncthreads();
    }

#pragma unroll
    for (int mi = 0; mi < 4; mi++) {
#pragma unroll
        for (int ni = 0; ni < 4; ni++) {
            const int row = m0 + wm * 64 + mi * 16 + gID;
            const int col = n0 + wn * 32 + ni * 8 + 2 * tig;
            const float bz0 = bias[col], bz1 = bias[col + 1];
            float2 v0 = make_float2(acc[mi][ni][0] + bz0, acc[mi][ni][1] + bz1);
            float2 v1 = make_float2(acc[mi][ni][2] + bz0, acc[mi][ni][3] + bz1);
            *(float2*)&g_xproj[(size_t)row * N3 + col]       = v0;
            *(float2*)&g_xproj[(size_t)(row + 8) * N3 + col] = v1;
        }
    }
}

// ---------------------------------------------------------------------------
// Kernel 2: persistent GRU scan — cluster-2 split-K, fp16 MMA, MONOLITHIC
// per-phase staging (one cp.async burst + one wait per phase; zero in-loop
// syncs). Otherwise R12-verbatim.
// SMEM (uint32/float units):
//   ws   [48][260]   @ 0      Wz(0-15)/Wr(16-31)/Wh(32-47) cols, fp16 pairs
//   stg  [64][260]   @ 12480  whole staged h/rh half-K slice (512 halfs/row)
//   pacc (alias stg) @ 12480  16x528 (A) / 16x272 (B), fp32
//   redA [64][33]    @ 29120
//   redB [64][17]    @ 31232
// total 32320 units = 129,280 B
// ---------------------------------------------------------------------------
#define SM_WS   0
#define SM_STG  12480
#define SM_PACC 12480
#define SM_REDA 29120
#define SM_REDB 31232
#define SMEM_FLOATS 32320

__global__ void __launch_bounds__(TPB, 1) __cluster_dims__(2, 1, 1)
gru_scan(const float* __restrict__ hidden,
         const float* __restrict__ rk,
         float* __restrict__ out)
{
    extern __shared__ float sm[];
    uint32_t* smu = (uint32_t*)sm;
    float* pacc = sm + SM_PACC;
    float* redA = sm + SM_REDA;
    float* redB = sm + SM_REDB;

    const int tid   = threadIdx.x;
    const int cta   = blockIdx.x;
    const int crank = cta & 1;        // cluster rank (k-half owner)
    const int cg    = cta >> 1;       // column group 0..63
    const uint32_t peer = crank ^ 1;

    const int wid  = tid >> 5;
    const int lane = tid & 31;
    const int gID  = lane >> 2;
    const int tig  = lane & 3;
    const int mg   = wid & 3;         // m-group: rows [mg*16, mg*16+16)
    const int ksl  = wid >> 2;        // k-slice 0..3
    const int r0   = mg * 16 + gID;

    // gate/update mapping: 32 rows x 16 cols per CTA
    const int grow = crank * 32 + (tid >> 4);
    const int gcol = cg * 16 + (tid & 15);
    const int lcol = tid & 15;

    // reduction mapping (all 64 rows for peer)
    const int rrow = tid >> 3;
    const int rc4  = (tid & 7) * 4;
    const int rc2  = (tid & 7) * 2;
    const int rmgr = rrow >> 4;
    const int rlr  = rrow & 15;

    const int koff = crank * 512;     // k base (half units)

    // ---- load weight slice as fp16 pairs (16 cols x 3 gates x 256 pairs) ----
    for (int idx = tid; idx < 48 * 256; idx += TPB) {
        const int r  = idx >> 8;                 // ws col-row 0..47
        const int kp = idx & 255;                // k-pair 0..255
        const int col = (r >> 4) * UNITS + cg * 16 + (r & 15);
        const float w0 = rk[(size_t)(koff + 2 * kp    ) * N3 + col];
        const float w1 = rk[(size_t)(koff + 2 * kp + 1) * N3 + col];
        smu[SM_WS + r * 260 + kp] = pack_h2(w0, w1);
    }

    // ---- init g_hx (fp16 of hidden) + register h ----
    float hreg;
    {
        int gidx = cta * TPB + tid;              // 128*512 = 65536 exactly
        g_hx[gidx] = __float2half_rn(hidden[gidx]);
        hreg = hidden[grow * UNITS + gcol];
    }
    unsigned bseq = 0;
    grid_barrier(++bseq * GRID);

    // monolithic staging: 8 x 16B per thread; row = sbrow + 8i, slot fixed
    const int sbrow = tid >> 6;                  // 0..7
    const int sslot = tid & 63;                  // 16B slot within 1024B row
    const uint32_t st_s = s2u(&smu[SM_STG + sbrow * 260 + sslot * 4]);
    const size_t gs_off = ((size_t)(sbrow * UNITS + koff)) * 2 + sslot * 16; // bytes

    const uint32_t* wsz0 = &smu[SM_WS + (gID     ) * 260];
    const uint32_t* wsz1 = &smu[SM_WS + (gID +  8) * 260];
    const uint32_t* wsr0 = &smu[SM_WS + (gID + 16) * 260];
    const uint32_t* wsr1 = &smu[SM_WS + (gID + 24) * 260];
    const uint32_t* wsh0 = &smu[SM_WS + (gID + 32) * 260];
    const uint32_t* wsh1 = &smu[SM_WS + (gID + 40) * 260];
    const int fcol = ksl * 8 + tig;              // frag pair-col within k-iter

    float zreg = 0.f;

    for (int t = 0; t < TLEN; t++) {
        const size_t xb = ((size_t)(grow * TLEN + t)) * N3 + gcol;
        const float xz = __ldcg(&g_xproj[xb]);
        const float xr = __ldcg(&g_xproj[xb + UNITS]);
        const float xh = __ldcg(&g_xproj[xb + 2 * UNITS]);

        // =================== Phase A: zr_partial = h @ [Wz|Wr] (half-K) ======
        {
            const char* src = (const char*)g_hx + gs_off;

            float az0[4], az1[4], ar0[4], ar1[4];
#pragma unroll
            for (int c = 0; c < 4; c++) { az0[c]=0.f; az1[c]=0.f; ar0[c]=0.f; ar1[c]=0.f; }

            // stage entire half-K slice in one burst
#pragma unroll
            for (int i = 0; i < 8; i++)
                cp_async16(st_s + i * (8 * 260 * 4), src + i * (8 * UNITS * 2));
            CP_COMMIT();
            CP_WAIT0();
            __syncthreads();

            const uint32_t* hb = &smu[SM_STG];
#pragma unroll
            for (int kc = 0; kc < NCHUNK; kc++) {
                const int kw = kc * 32 + fcol;
                uint32_t a0 = hb[(r0    ) * 260 + kw];
                uint32_t a1 = hb[(r0 + 8) * 260 + kw];
                uint32_t a2 = hb[(r0    ) * 260 + kw + 4];
                uint32_t a3 = hb[(r0 + 8) * 260 + kw + 4];
                MMA_F16(az0[0], az0[1], az0[2], az0[3], a0, a1, a2, a3, wsz0[kw], wsz0[kw + 4]);
                MMA_F16(az1[0], az1[1], az1[2], az1[3], a0, a1, a2, a3, wsz1[kw], wsz1[kw + 4]);
                MMA_F16(ar0[0], ar0[1], ar0[2], ar0[3], a0, a1, a2, a3, wsr0[kw], wsr0[kw + 4]);
                MMA_F16(ar1[0], ar1[1], ar1[2], ar1[3], a0, a1, a2, a3, wsr1[kw], wsr1[kw + 4]);
            }

            __syncthreads();   // all reads of stage done before pacc alias

            // warp partials: C[16x32], row stride 33
            float* pw = pacc + wid * 528;
            pw[(gID    ) * 33 +  0 + 2 * tig    ] = az0[0];
            pw[(gID    ) * 33 +  0 + 2 * tig + 1] = az0[1];
            pw[(gID + 8) * 33 +  0 + 2 * tig    ] = az0[2];
            pw[(gID + 8) * 33 +  0 + 2 * tig + 1] = az0[3];
            pw[(gID    ) * 33 +  8 + 2 * tig    ] = az1[0];
            pw[(gID    ) * 33 +  8 + 2 * tig + 1] = az1[1];
            pw[(gID + 8) * 33 +  8 + 2 * tig    ] = az1[2];
            pw[(gID + 8) * 33 +  8 + 2 * tig + 1] = az1[3];
            pw[(gID    ) * 33 + 16 + 2 * tig    ] = ar0[0];
            pw[(gID    ) * 33 + 16 + 2 * tig + 1] = ar0[1];
            pw[(gID + 8) * 33 + 16 + 2 * tig    ] = ar0[2];
            pw[(gID + 8) * 33 + 16 + 2 * tig + 1] = ar0[3];
            pw[(gID    ) * 33 + 24 + 2 * tig    ] = ar1[0];
            pw[(gID    ) * 33 + 24 + 2 * tig + 1] = ar1[1];
            pw[(gID + 8) * 33 + 24 + 2 * tig    ] = ar1[2];
            pw[(gID + 8) * 33 + 24 + 2 * tig + 1] = ar1[3];
            __syncthreads();

            // reduce 4 k-slices -> redA[64][33]
            {
                float s0 = 0.f, s1 = 0.f, s2 = 0.f, s3 = 0.f;
#pragma unroll
                for (int s = 0; s < 4; s++) {
                    const float* p = pacc + (s * 4 + rmgr) * 528 + rlr * 33 + rc4;
                    s0 += p[0]; s1 += p[1]; s2 += p[2]; s3 += p[3];
                }
                float* rd = redA + rrow * 33 + rc4;
                rd[0] = s0; rd[1] = s1; rd[2] = s2; rd[3] = s3;
            }
            CLUSTER_SYNC();

            // gates: own + peer half-K partial (DSMEM)
            {
                const uint32_t zloc = s2u(&redA[grow * 33 + lcol]);
                const uint32_t rloc = s2u(&redA[grow * 33 + 16 + lcol]);
                float zp = sm[SM_REDA + grow * 33 + lcol]      + dsmem_ld(zloc, peer);
                float rp = sm[SM_REDA + grow * 33 + 16 + lcol] + dsmem_ld(rloc, peer);
                float z = 1.f / (1.f + __expf(-(xz + zp)));
                float r = 1.f / (1.f + __expf(-(xr + rp)));
                g_rhx[grow * UNITS + gcol] = __float2half_rn(r * hreg);
                zreg = z;
            }
        }
        grid_barrier(++bseq * GRID);

        // =================== Phase B: mh_partial = rh @ Wh (half-K) ==========
        {
            const char* src = (const char*)g_rhx + gs_off;

            float ah0[4], ah1[4];
#pragma unroll
            for (int c = 0; c < 4; c++) { ah0[c] = 0.f; ah1[c] = 0.f; }

#pragma unroll
            for (int i = 0; i < 8; i++)
                cp_async16(st_s + i * (8 * 260 * 4), src + i * (8 * UNITS * 2));
            CP_COMMIT();
            CP_WAIT0();
            __syncthreads();

            const uint32_t* hb = &smu[SM_STG];
#pragma unroll
            for (int kc = 0; kc < NCHUNK; kc++) {
                const int kw = kc * 32 + fcol;
                uint32_t a0 = hb[(r0    ) * 260 + kw];
                uint32_t a1 = hb[(r0 + 8) * 260 + kw];
                uint32_t a2 = hb[(r0    ) * 260 + kw + 4];
                uint32_t a3 = hb[(r0 + 8) * 260 + kw + 4];
                MMA_F16(ah0[0], ah0[1], ah0[2], ah0[3], a0, a1, a2, a3, wsh0[kw], wsh0[kw + 4]);
                MMA_F16(ah1[0], ah1[1], ah1[2], ah1[3], a0, a1, a2, a3, wsh1[kw], wsh1[kw + 4]);
            }

            __syncthreads();

            // warp partials: C[16x16], row stride 17
            float* pw = pacc + wid * 272;
            pw[(gID    ) * 17 + 0 + 2 * tig    ] = ah0[0];
            pw[(gID    ) * 17 + 0 + 2 * tig + 1] = ah0[1];
            pw[(gID + 8) * 17 + 0 + 2 * tig    ] = ah0[2];
            pw[(gID + 8) * 17 + 0 + 2 * tig + 1] = ah0[3];
            pw[(gID    ) * 17 + 8 + 2 * tig    ] = ah1[0];
            pw[(gID    ) * 17 + 8 + 2 * tig + 1] = ah1[1];
            pw[(gID + 8) * 17 + 8 + 2 * tig    ] = ah1[2];
            pw[(gID + 8) * 17 + 8 + 2 * tig + 1] = ah1[3];
            __syncthreads();

            // reduce 4 k-slices -> redB[64][17]
            {
                float s0 = 0.f, s1 = 0.f;
#pragma unroll
                for (int s = 0; s < 4; s++) {
                    const float* p = pacc + (s * 4 + rmgr) * 272 + rlr * 17 + rc2;
                    s0 += p[0]; s1 += p[1];
                }
                float* rd = redB + rrow * 17 + rc2;
                rd[0] = s0; rd[1] = s1;
            }
            CLUSTER_SYNC();

            // h update: own + peer partial
            {
                const uint32_t hlocA = s2u(&redB[grow * 17 + lcol]);
                float mp = sm[SM_REDB + grow * 17 + lcol] + dsmem_ld(hlocA, peer);
                const float a = xh + mp;
                const float hh = 1.f - 2.f / (1.f + __expf(2.f * a));  // tanh(a)
                const float hn = zreg * hreg + (1.f - zreg) * hh;
                hreg = hn;
                g_hx[grow * UNITS + gcol] = __float2half_rn(hn);
                out[((size_t)(grow * TLEN + t)) * UNITS + gcol] = hn;
                if (t == TLEN - 1)
                    out[(size_t)BATCH * TLEN * UNITS + (size_t)grow * UNITS + gcol] = hn;
            }
        }
        grid_barrier(++bseq * GRID);
    }
}

// ---------------------------------------------------------------------------
extern "C" void kernel_launch(void* const* d_in, const int* in_sizes, int n_in,
                              void* d_out, int out_size)
{
    const int*   x      = (const int*)d_in[0];
    const float* hidden = (const float*)d_in[1];
    const float* emb    = (const float*)d_in[2];
    const float* kern   = (const float*)d_in[3];
    const float* rk     = (const float*)d_in[4];
    const float* bias   = (const float*)d_in[5];
    float* out = (float*)d_out;

    static bool attr_set = false;
    if (!attr_set) {
        cudaFuncSetAttribute(gru_scan, cudaFuncAttributeMaxDynamicSharedMemorySize,
                             SMEM_FLOATS * sizeof(float));
        attr_set = true;
    }

    // Node 1: projection GEMM (tf32, cp.async pipelined) + barrier reset
    xproj_tf32<<<dim3(N3 / 128, (BATCH * TLEN) / 128), 256>>>(x, emb, kern, bias);

    // Node 2: persistent GRU scan (cluster-2 split-K, fp16, monolithic stage)
    gru_scan<<<GRID, TPB, SMEM_FLOATS * sizeof(float)>>>(hidden, rk, out);
}

// round 14
// speedup vs baseline: 2.1951x; 1.0287x over previous
#include <cuda_runtime.h>
#include <cuda_fp16.h>
#include <cstdint>

#define VOCAB 32000
#define EMB   256
#define UNITS 1024
#define BATCH 64
#define TLEN  512
#define N3    3072

#define GRID  128
#define TPB   512

// -------------------- device globals (no allocation allowed) ---------------
__device__ float g_xproj[(size_t)BATCH * TLEN * N3];            // [B*T, 3U]
__device__ __align__(16) __half g_hx[BATCH * UNITS];            // h  (fp16)
__device__ __align__(16) __half g_rhx[BATCH * UNITS];           // r*h (fp16)
__device__ unsigned g_count = 0;

// -------------------- helpers ----------------------------------------------
__device__ __forceinline__ uint32_t f2tf32(float x) {
    uint32_t r;
    asm("cvt.rna.tf32.f32 %0, %1;" : "=r"(r) : "f"(x));
    return r;
}

__device__ __forceinline__ uint32_t pack_h2(float lo, float hi) {
    __half2 h = __floats2half2_rn(lo, hi);
    return *(uint32_t*)&h;
}

__device__ __forceinline__ uint32_t s2u(const void* p) {
    uint32_t a;
    asm("{ .reg .u64 t; cvta.to.shared.u64 t, %1; cvt.u32.u64 %0, t; }"
        : "=r"(a) : "l"(p));
    return a;
}

__device__ __forceinline__ void cp_async16(uint32_t saddr, const void* gaddr) {
    asm volatile("cp.async.cg.shared.global [%0], [%1], 16;"
                 :: "r"(saddr), "l"(gaddr));
}
#define CP_COMMIT() asm volatile("cp.async.commit_group;")
#define CP_WAIT0()  asm volatile("cp.async.wait_group 0;")
#define CP_WAIT1()  asm volatile("cp.async.wait_group 1;")

#define MMA_TF32(d0,d1,d2,d3,a0,a1,a2,a3,b0,b1)                               \
    asm volatile(                                                             \
        "mma.sync.aligned.m16n8k8.row.col.f32.tf32.tf32.f32 "                 \
        "{%0,%1,%2,%3},{%4,%5,%6,%7},{%8,%9},{%0,%1,%2,%3};"                  \
        : "+f"(d0), "+f"(d1), "+f"(d2), "+f"(d3)                              \
        : "r"(a0), "r"(a1), "r"(a2), "r"(a3), "r"(b0), "r"(b1))

#define MMA_F16(d0,d1,d2,d3,a0,a1,a2,a3,b0,b1)                                \
    asm volatile(                                                             \
        "mma.sync.aligned.m16n8k16.row.col.f32.f16.f16.f32 "                  \
        "{%0,%1,%2,%3},{%4,%5,%6,%7},{%8,%9},{%0,%1,%2,%3};"                  \
        : "+f"(d0), "+f"(d1), "+f"(d2), "+f"(d3)                              \
        : "r"(a0), "r"(a1), "r"(a2), "r"(a3), "r"(b0), "r"(b1))

#define CLUSTER_SYNC() do {                                                   \
    asm volatile("barrier.cluster.arrive.aligned;" ::: "memory");             \
    asm volatile("barrier.cluster.wait.aligned;"   ::: "memory");             \
} while (0)

__device__ __forceinline__ float dsmem_ld(uint32_t saddr, uint32_t rank) {
    uint32_t ra;
    asm("mapa.shared::cluster.u32 %0, %1, %2;" : "=r"(ra) : "r"(saddr), "r"(rank));
    float v;
    asm volatile("ld.shared::cluster.f32 %0, [%1];" : "=f"(v) : "r"(ra));
    return v;
}

// -------------------- grid barrier: monotonic release/acquire --------------
__device__ __forceinline__ void grid_barrier(unsigned target)
{
    __syncthreads();
    if (threadIdx.x == 0) {
        unsigned* cnt = &g_count;
        asm volatile("red.release.gpu.global.add.u32 [%0], %1;"
                     :: "l"(cnt), "r"(1u) : "memory");
        unsigned v;
        do {
            asm volatile("ld.acquire.gpu.global.u32 %0, [%1];"
                         : "=r"(v) : "l"(cnt) : "memory");
        } while (v < target);
    }
    __syncthreads();
}

// ---------------------------------------------------------------------------
// Kernel 1: xproj = gather(emb_table, x) @ kernel + bias — tf32 mma.sync,
// cp.async double-buffered (R11-verbatim, verified). Resets g_count.
// ---------------------------------------------------------------------------
#define XKC   16
#define XNCH  (EMB / XKC)
#define ASTR  20
#define BSTR  136

__global__ __launch_bounds__(256) void xproj_tf32(
    const int* __restrict__ x,
    const float* __restrict__ emb_table,
    const float* __restrict__ kernelW,
    const float* __restrict__ bias)
{
    if (blockIdx.x == 0 && blockIdx.y == 0 && threadIdx.x == 0)
        g_count = 0;

    __shared__ __align__(16) float As[2][128 * ASTR];
    __shared__ __align__(16) float Bs[2][XKC * BSTR];

    const int tid  = threadIdx.x;
    const int wid  = tid >> 5;
    const int lane = tid & 31;
    const int gID  = lane >> 2;
    const int tig  = lane & 3;
    const int wm   = wid & 1;
    const int wn   = wid >> 1;

    const int m0 = blockIdx.y * 128;
    const int n0 = blockIdx.x * 128;

    const int arow = tid & 127;
    const int ahalf = tid >> 7;
    const int token = x[m0 + arow];
    const float* aptr = emb_table + (size_t)token * EMB;
    const uint32_t a_s0 = s2u(&As[0][arow * ASTR + ahalf * 8]);
    const int abuf_delta = (int)(s2u(&As[1][0]) - s2u(&As[0][0]));

    const int bkrow = tid >> 4;
    const int bseg  = tid & 15;
    const uint32_t b_s0 = s2u(&Bs[0][bkrow * BSTR + bseg * 8]);
    const int bbuf_delta = (int)(s2u(&Bs[1][0]) - s2u(&Bs[0][0]));

    float acc[4][4][4];
#pragma unroll
    for (int mi = 0; mi < 4; mi++)
#pragma unroll
        for (int ni = 0; ni < 4; ni++)
#pragma unroll
            for (int c = 0; c < 4; c++) acc[mi][ni][c] = 0.f;

    {
        const float* ag = aptr + ahalf * 8;
        cp_async16(a_s0,      ag);
        cp_async16(a_s0 + 16, ag + 4);
        const float* bg = kernelW + (size_t)bkrow * N3 + n0 + bseg * 8;
        cp_async16(b_s0,      bg);
        cp_async16(b_s0 + 16, bg + 4);
        CP_COMMIT();
    }

    for (int kc = 0; kc < XNCH; kc++) {
        const int buf = kc & 1;
        if (kc + 1 < XNCH) {
            const int nb = (kc + 1) & 1;
            const float* ag = aptr + (kc + 1) * XKC + ahalf * 8;
            cp_async16(a_s0 + nb * abuf_delta,      ag);
            cp_async16(a_s0 + nb * abuf_delta + 16, ag + 4);
            const float* bg = kernelW + (size_t)((kc + 1) * XKC + bkrow) * N3 + n0 + bseg * 8;
            cp_async16(b_s0 + nb * bbuf_delta,      bg);
            cp_async16(b_s0 + nb * bbuf_delta + 16, bg + 4);
            CP_COMMIT();
            CP_WAIT1();
        } else {
            CP_WAIT0();
        }
        __syncthreads();

        const float* Ab = As[buf];
        const float* Bb = Bs[buf];
#pragma unroll
        for (int kt = 0; kt < 2; kt++) {
            const int kb = kt * 8;
            uint32_t af[4][4], bf[4][2];
#pragma unroll
            for (int mi = 0; mi < 4; mi++) {
                const int mr = wm * 64 + mi * 16;
                af[mi][0] = f2tf32(Ab[(mr + gID    ) * ASTR + kb + tig]);
                af[mi][1] = f2tf32(Ab[(mr + gID + 8) * ASTR + kb + tig]);
                af[mi][2] = f2tf32(Ab[(mr + gID    ) * ASTR + kb + tig + 4]);
                af[mi][3] = f2tf32(Ab[(mr + gID + 8) * ASTR + kb + tig + 4]);
            }
#pragma unroll
            for (int ni = 0; ni < 4; ni++) {
                const int nb2 = wn * 32 + ni * 8 + gID;
                bf[ni][0] = f2tf32(Bb[(kb + tig    ) * BSTR + nb2]);
                bf[ni][1] = f2tf32(Bb[(kb + tig + 4) * BSTR + nb2]);
            }
#pragma unroll
            for (int mi = 0; mi < 4; mi++)
#pragma unroll
                for (int ni = 0; ni < 4; ni++)
                    MMA_TF32(acc[mi][ni][0], acc[mi][ni][1],
                             acc[mi][ni][2], acc[mi][ni][3],
                             af[mi][0], af[mi][1], af[mi][2], af[mi][3],
                             bf[ni][0], bf[ni][1]);
        }
        __syncthreads();
    }

#pragma unroll
    for (int mi = 0; mi < 4; mi++) {
#pragma unroll
        for (int ni = 0; ni < 4; ni++) {
            const int row = m0 + wm * 64 + mi * 16 + gID;
            const int col = n0 + wn * 32 + ni * 8 + 2 * tig;
            const float bz0 = bias[col], bz1 = bias[col + 1];
            float2 v0 = make_float2(acc[mi][ni][0] + bz0, acc[mi][ni][1] + bz1);
            float2 v1 = make_float2(acc[mi][ni][2] + bz0, acc[mi][ni][3] + bz1);
            *(float2*)&g_xproj[(size_t)row * N3 + col]       = v0;
            *(float2*)&g_xproj[(size_t)(row + 8) * N3 + col] = v1;
        }
    }
}

// ---------------------------------------------------------------------------
// Kernel 2: persistent GRU scan — cluster-2 split-K, fp16 MMA, 2-CHUNK
// pipelined staging (both chunks committed up-front; compute chunk0 while
// chunk1 lands). Otherwise R13-verbatim.
// SMEM (uint32/float units):
//   ws   [48][260]    @ 0      Wz(0-15)/Wr(16-31)/Wh(32-47) cols, fp16 pairs
//   stg  [2][64][132] @ 12480  staged h/rh half-K slice, 2 chunks of 256 halfs
//   pacc (alias stg)  @ 12480  16x528 (A) / 16x272 (B), fp32
//   redA [64][33]     @ 29376
//   redB [64][17]     @ 31488
// total 32576 units = 130,304 B
// ---------------------------------------------------------------------------
#define SM_WS   0
#define SM_STG  12480
#define CHUNKU  8448       // 64 * 132 u32 per chunk buffer
#define SM_PACC 12480
#define SM_REDA 29376
#define SM_REDB 31488
#define SMEM_FLOATS 32576

__global__ void __launch_bounds__(TPB, 1) __cluster_dims__(2, 1, 1)
gru_scan(const float* __restrict__ hidden,
         const float* __restrict__ rk,
         float* __restrict__ out)
{
    extern __shared__ float sm[];
    uint32_t* smu = (uint32_t*)sm;
    float* pacc = sm + SM_PACC;
    float* redA = sm + SM_REDA;
    float* redB = sm + SM_REDB;

    const int tid   = threadIdx.x;
    const int cta   = blockIdx.x;
    const int crank = cta & 1;        // cluster rank (k-half owner)
    const int cg    = cta >> 1;       // column group 0..63
    const uint32_t peer = crank ^ 1;

    const int wid  = tid >> 5;
    const int lane = tid & 31;
    const int gID  = lane >> 2;
    const int tig  = lane & 3;
    const int mg   = wid & 3;         // m-group: rows [mg*16, mg*16+16)
    const int ksl  = wid >> 2;        // k-slice 0..3
    const int r0   = mg * 16 + gID;

    // gate/update mapping: 32 rows x 16 cols per CTA
    const int grow = crank * 32 + (tid >> 4);
    const int gcol = cg * 16 + (tid & 15);
    const int lcol = tid & 15;

    // reduction mapping (all 64 rows for peer)
    const int rrow = tid >> 3;
    const int rc4  = (tid & 7) * 4;
    const int rc2  = (tid & 7) * 2;
    const int rmgr = rrow >> 4;
    const int rlr  = rrow & 15;

    const int koff = crank * 512;     // k base (half units)

    // ---- load weight slice as fp16 pairs (16 cols x 3 gates x 256 pairs) ----
    for (int idx = tid; idx < 48 * 256; idx += TPB) {
        const int r  = idx >> 8;                 // ws col-row 0..47
        const int kp = idx & 255;                // k-pair 0..255
        const int col = (r >> 4) * UNITS + cg * 16 + (r & 15);
        const float w0 = rk[(size_t)(koff + 2 * kp    ) * N3 + col];
        const float w1 = rk[(size_t)(koff + 2 * kp + 1) * N3 + col];
        smu[SM_WS + r * 260 + kp] = pack_h2(w0, w1);
    }

    // ---- init g_hx (fp16 of hidden) + register h ----
    float hreg;
    {
        int gidx = cta * TPB + tid;              // 128*512 = 65536 exactly
        g_hx[gidx] = __float2half_rn(hidden[gidx]);
        hreg = hidden[grow * UNITS + gcol];
    }
    unsigned bseq = 0;
    grid_barrier(++bseq * GRID);

    // staging: per chunk, 4 x 16B per thread; chunk = 256 halfs/row = 512B/row
    int st_r[4], st_c[4];
    uint32_t st_s[4];
#pragma unroll
    for (int i = 0; i < 4; i++) {
        int flat = i * TPB + tid;               // 0..2047
        st_r[i] = flat >> 5;                    // row 0..63
        st_c[i] = flat & 31;                    // 16B slot 0..31
        st_s[i] = s2u(&smu[SM_STG + st_r[i] * 132 + st_c[i] * 4]);
    }

    const uint32_t* wsz0 = &smu[SM_WS + (gID     ) * 260];
    const uint32_t* wsz1 = &smu[SM_WS + (gID +  8) * 260];
    const uint32_t* wsr0 = &smu[SM_WS + (gID + 16) * 260];
    const uint32_t* wsr1 = &smu[SM_WS + (gID + 24) * 260];
    const uint32_t* wsh0 = &smu[SM_WS + (gID + 32) * 260];
    const uint32_t* wsh1 = &smu[SM_WS + (gID + 40) * 260];
    const int fcol = ksl * 8 + tig;              // frag pair-col within k-iter

    float zreg = 0.f;

    for (int t = 0; t < TLEN; t++) {
        const size_t xb = ((size_t)(grow * TLEN + t)) * N3 + gcol;
        const float xz = __ldcg(&g_xproj[xb]);
        const float xr = __ldcg(&g_xproj[xb + UNITS]);
        const float xh = __ldcg(&g_xproj[xb + 2 * UNITS]);

        // =================== Phase A: zr_partial = h @ [Wz|Wr] (half-K) ======
        {
            const char* src = (const char*)g_hx;

            float az0[4], az1[4], ar0[4], ar1[4];
#pragma unroll
            for (int c = 0; c < 4; c++) { az0[c]=0.f; az1[c]=0.f; ar0[c]=0.f; ar1[c]=0.f; }

            // commit both chunks up-front (chunk 0 first -> completes first)
#pragma unroll
            for (int cchunk = 0; cchunk < 2; cchunk++) {
#pragma unroll
                for (int i = 0; i < 4; i++)
                    cp_async16(st_s[i] + cchunk * (CHUNKU * 4),
                               src + ((size_t)(st_r[i] * UNITS + koff)) * 2
                                   + cchunk * 512 + st_c[i] * 16);
                CP_COMMIT();
            }

            CP_WAIT1();
            __syncthreads();
#pragma unroll
            for (int kc = 0; kc < 4; kc++) {
                const int kw = kc * 32 + fcol;           // weight index (full)
                const uint32_t* hb = &smu[SM_STG];
                uint32_t a0 = hb[(r0    ) * 132 + kw];
                uint32_t a1 = hb[(r0 + 8) * 132 + kw];
                uint32_t a2 = hb[(r0    ) * 132 + kw + 4];
                uint32_t a3 = hb[(r0 + 8) * 132 + kw + 4];
                MMA_F16(az0[0], az0[1], az0[2], az0[3], a0, a1, a2, a3, wsz0[kw], wsz0[kw + 4]);
                MMA_F16(az1[0], az1[1], az1[2], az1[3], a0, a1, a2, a3, wsz1[kw], wsz1[kw + 4]);
                MMA_F16(ar0[0], ar0[1], ar0[2], ar0[3], a0, a1, a2, a3, wsr0[kw], wsr0[kw + 4]);
                MMA_F16(ar1[0], ar1[1], ar1[2], ar1[3], a0, a1, a2, a3, wsr1[kw], wsr1[kw + 4]);
            }
            CP_WAIT0();
            __syncthreads();
#pragma unroll
            for (int kc = 0; kc < 4; kc++) {
                const int kwl = kc * 32 + fcol;          // local index in chunk1
                const int kw  = 128 + kwl;               // weight index (full)
                const uint32_t* hb = &smu[SM_STG + CHUNKU];
                uint32_t a0 = hb[(r0    ) * 132 + kwl];
                uint32_t a1 = hb[(r0 + 8) * 132 + kwl];
                uint32_t a2 = hb[(r0    ) * 132 + kwl + 4];
                uint32_t a3 = hb[(r0 + 8) * 132 + kwl + 4];
                MMA_F16(az0[0], az0[1], az0[2], az0[3], a0, a1, a2, a3, wsz0[kw], wsz0[kw + 4]);
                MMA_F16(az1[0], az1[1], az1[2], az1[3], a0, a1, a2, a3, wsz1[kw], wsz1[kw + 4]);
                MMA_F16(ar0[0], ar0[1], ar0[2], ar0[3], a0, a1, a2, a3, wsr0[kw], wsr0[kw + 4]);
                MMA_F16(ar1[0], ar1[1], ar1[2], ar1[3], a0, a1, a2, a3, wsr1[kw], wsr1[kw + 4]);
            }

            __syncthreads();   // all reads of stage done before pacc alias

            // warp partials: C[16x32], row stride 33
            float* pw = pacc + wid * 528;
            pw[(gID    ) * 33 +  0 + 2 * tig    ] = az0[0];
            pw[(gID    ) * 33 +  0 + 2 * tig + 1] = az0[1];
            pw[(gID + 8) * 33 +  0 + 2 * tig    ] = az0[2];
            pw[(gID + 8) * 33 +  0 + 2 * tig + 1] = az0[3];
            pw[(gID    ) * 33 +  8 + 2 * tig    ] = az1[0];
            pw[(gID    ) * 33 +  8 + 2 * tig + 1] = az1[1];
            pw[(gID + 8) * 33 +  8 + 2 * tig    ] = az1[2];
            pw[(gID + 8) * 33 +  8 + 2 * tig + 1] = az1[3];
            pw[(gID    ) * 33 + 16 + 2 * tig    ] = ar0[0];
            pw[(gID    ) * 33 + 16 + 2 * tig + 1] = ar0[1];
            pw[(gID + 8) * 33 + 16 + 2 * tig    ] = ar0[2];
            pw[(gID + 8) * 33 + 16 + 2 * tig + 1] = ar0[3];
            pw[(gID    ) * 33 + 24 + 2 * tig    ] = ar1[0];
            pw[(gID    ) * 33 + 24 + 2 * tig + 1] = ar1[1];
            pw[(gID + 8) * 33 + 24 + 2 * tig    ] = ar1[2];
            pw[(gID + 8) * 33 + 24 + 2 * tig + 1] = ar1[3];
            __syncthreads();

            // reduce 4 k-slices -> redA[64][33]
            {
                float s0 = 0.f, s1 = 0.f, s2 = 0.f, s3 = 0.f;
#pragma unroll
                for (int s = 0; s < 4; s++) {
                    const float* p = pacc + (s * 4 + rmgr) * 528 + rlr * 33 + rc4;
                    s0 += p[0]; s1 += p[1]; s2 += p[2]; s3 += p[3];
                }
                float* rd = redA + rrow * 33 + rc4;
                rd[0] = s0; rd[1] = s1; rd[2] = s2; rd[3] = s3;
            }
            CLUSTER_SYNC();

            // gates: own + peer half-K partial (DSMEM)
            {
                const uint32_t zloc = s2u(&redA[grow * 33 + lcol]);
                const uint32_t rloc = s2u(&redA[grow * 33 + 16 + lcol]);
                float zp = sm[SM_REDA + grow * 33 + lcol]      + dsmem_ld(zloc, peer);
                float rp = sm[SM_REDA + grow * 33 + 16 + lcol] + dsmem_ld(rloc, peer);
                float z = 1.f / (1.f + __expf(-(xz + zp)));
                float r = 1.f / (1.f + __expf(-(xr + rp)));
                g_rhx[grow * UNITS + gcol] = __float2half_rn(r * hreg);
                zreg = z;
            }
        }
        grid_barrier(++bseq * GRID);

        // =================== Phase B: mh_partial = rh @ Wh (half-K) ==========
        {
            const char* src = (const char*)g_rhx;

            float ah0[4], ah1[4];
#pragma unroll
            for (int c = 0; c < 4; c++) { ah0[c] = 0.f; ah1[c] = 0.f; }

#pragma unroll
            for (int cchunk = 0; cchunk < 2; cchunk++) {
#pragma unroll
                for (int i = 0; i < 4; i++)
                    cp_async16(st_s[i] + cchunk * (CHUNKU * 4),
                               src + ((size_t)(st_r[i] * UNITS + koff)) * 2
                                   + cchunk * 512 + st_c[i] * 16);
                CP_COMMIT();
            }

            CP_WAIT1();
            __syncthreads();
#pragma unroll
            for (int kc = 0; kc < 4; kc++) {
                const int kw = kc * 32 + fcol;
                const uint32_t* hb = &smu[SM_STG];
                uint32_t a0 = hb[(r0    ) * 132 + kw];
                uint32_t a1 = hb[(r0 + 8) * 132 + kw];
                uint32_t a2 = hb[(r0    ) * 132 + kw + 4];
                uint32_t a3 = hb[(r0 + 8) * 132 + kw + 4];
                MMA_F16(ah0[0], ah0[1], ah0[2], ah0[3], a0, a1, a2, a3, wsh0[kw], wsh0[kw + 4]);
                MMA_F16(ah1[0], ah1[1], ah1[2], ah1[3], a0, a1, a2, a3, wsh1[kw], wsh1[kw + 4]);
            }
            CP_WAIT0();
            __syncthreads();
#pragma unroll
            for (int kc = 0; kc < 4; kc++) {
                const int kwl = kc * 32 + fcol;
                const int kw  = 128 + kwl;
                const uint32_t* hb = &smu[SM_STG + CHUNKU];
                uint32_t a0 = hb[(r0    ) * 132 + kwl];
                uint32_t a1 = hb[(r0 + 8) * 132 + kwl];
                uint32_t a2 = hb[(r0    ) * 132 + kwl + 4];
                uint32_t a3 = hb[(r0 + 8) * 132 + kwl + 4];
                MMA_F16(ah0[0], ah0[1], ah0[2], ah0[3], a0, a1, a2, a3, wsh0[kw], wsh0[kw + 4]);
                MMA_F16(ah1[0], ah1[1], ah1[2], ah1[3], a0, a1, a2, a3, wsh1[kw], wsh1[kw + 4]);
            }

            __syncthreads();

            // warp partials: C[16x16], row stride 17
            float* pw = pacc + wid * 272;
            pw[(gID    ) * 17 + 0 + 2 * tig    ] = ah0[0];
            pw[(gID    ) * 17 + 0 + 2 * tig + 1] = ah0[1];
            pw[(gID + 8) * 17 + 0 + 2 * tig    ] = ah0[2];
            pw[(gID + 8) * 17 + 0 + 2 * tig + 1] = ah0[3];
            pw[(gID    ) * 17 + 8 + 2 * tig    ] = ah1[0];
            pw[(gID    ) * 17 + 8 + 2 * tig + 1] = ah1[1];
            pw[(gID + 8) * 17 + 8 + 2 * tig    ] = ah1[2];
            pw[(gID + 8) * 17 + 8 + 2 * tig + 1] = ah1[3];
            __syncthreads();

            // reduce 4 k-slices -> redB[64][17]
            {
                float s0 = 0.f, s1 = 0.f;
#pragma unroll
                for (int s = 0; s < 4; s++) {
                    const float* p = pacc + (s * 4 + rmgr) * 272 + rlr * 17 + rc2;
                    s0 += p[0]; s1 += p[1];
                }
                float* rd = redB + rrow * 17 + rc2;
                rd[0] = s0; rd[1] = s1;
            }
            CLUSTER_SYNC();

            // h update: own + peer partial
            {
                const uint32_t hlocA = s2u(&redB[grow * 17 + lcol]);
                float mp = sm[SM_REDB + grow * 17 + lcol] + dsmem_ld(hlocA, peer);
                const float a = xh + mp;
                const float hh = 1.f - 2.f / (1.f + __expf(2.f * a));  // tanh(a)
                const float hn = zreg * hreg + (1.f - zreg) * hh;
                hreg = hn;
                g_hx[grow * UNITS + gcol] = __float2half_rn(hn);
                out[((size_t)(grow * TLEN + t)) * UNITS + gcol] = hn;
                if (t == TLEN - 1)
                    out[(size_t)BATCH * TLEN * UNITS + (size_t)grow * UNITS + gcol] = hn;
            }
        }
        grid_barrier(++bseq * GRID);
    }
}

// ---------------------------------------------------------------------------
extern "C" void kernel_launch(void* const* d_in, const int* in_sizes, int n_in,
                              void* d_out, int out_size)
{
    const int*   x      = (const int*)d_in[0];
    const float* hidden = (const float*)d_in[1];
    const float* emb    = (const float*)d_in[2];
    const float* kern   = (const float*)d_in[3];
    const float* rk     = (const float*)d_in[4];
    const float* bias   = (const float*)d_in[5];
    float* out = (float*)d_out;

    static bool attr_set = false;
    if (!attr_set) {
        cudaFuncSetAttribute(gru_scan, cudaFuncAttributeMaxDynamicSharedMemorySize,
                             SMEM_FLOATS * sizeof(float));
        attr_set = true;
    }

    // Node 1: projection GEMM (tf32, cp.async pipelined) + barrier reset
    xproj_tf32<<<dim3(N3 / 128, (BATCH * TLEN) / 128), 256>>>(x, emb, kern, bias);

    // Node 2: persistent GRU scan (cluster-2 split-K, fp16, 2-chunk pipeline)
    gru_scan<<<GRID, TPB, SMEM_FLOATS * sizeof(float)>>>(hidden, rk, out);
}